// round 1
// baseline (speedup 1.0000x reference)
#include <cuda_runtime.h>

// ---------------------------------------------------------------------------
// Problem dims
// ---------------------------------------------------------------------------
#define Bv   128
#define LTv  96
#define LIv  64
#define Dv   1024
#define Hv   4
#define DHv  256          // D / H
#define DTv  1024
#define DIv  2048
#define BHv  (Bv * Hv)    // 512

#define NEGF (-2147483648.0f)   // -2^31, exactly representable

// ---------------------------------------------------------------------------
// Scratch buffers (static device globals -- no runtime allocation)
// ---------------------------------------------------------------------------
static __device__ float g_Pt[(size_t)Bv * LTv * Dv];   // text_proj   [12288,1024]
static __device__ float g_Pi[(size_t)Bv * LIv * Dv];   // image_proj  [8192,1024]
static __device__ float g_Qb[(size_t)Bv * LTv * Dv];
static __device__ float g_Kb[(size_t)Bv * LTv * Dv];
static __device__ float g_Vb[(size_t)Bv * LTv * Dv];
static __device__ float g_Sb[(size_t)BHv * 96 * 96];   // scores, max 512*96*96
static __device__ float g_AO[(size_t)Bv * LTv * Dv];
static __device__ float g_Xt[(size_t)Bv * LIv * Dv];   // text branch after cross-attn LN
static __device__ float g_Xi[(size_t)Bv * LTv * Dv];   // image branch after cross-attn LN

// ---------------------------------------------------------------------------
// SGEMM: C[M,N] = A[M,K] @ W[K,N] (+ bias). Row-major everywhere.
// BM=BN=128, BK=8, 256 threads, 8x8 per-thread tile.
// Requires: M%128==0, N%128==0, K%8==0 (true for all call sites).
// ---------------------------------------------------------------------------
__global__ void __launch_bounds__(256)
sgemm_kernel(const float* __restrict__ A, const float* __restrict__ W,
             const float* __restrict__ bias, float* __restrict__ C,
             int M, int N, int K)
{
    __shared__ float As[8][128];
    __shared__ float Ws[8][128];

    const int tid = threadIdx.x;
    const int tx  = tid & 15;           // N direction (x8)
    const int ty  = tid >> 4;           // M direction (x8)
    const int bm  = blockIdx.y * 128;
    const int bn  = blockIdx.x * 128;

    const int arow = tid >> 1;          // 0..127
    const int acol = (tid & 1) << 2;    // 0 or 4
    const int wrow = tid >> 5;          // 0..7
    const int wcol = (tid & 31) << 2;   // 0..124

    const float* Ap = A + (size_t)(bm + arow) * K + acol;
    const float* Wp = W + (size_t)wrow * N + bn + wcol;

    float acc[8][8];
#pragma unroll
    for (int i = 0; i < 8; i++)
#pragma unroll
        for (int j = 0; j < 8; j++) acc[i][j] = 0.0f;

    for (int kk = 0; kk < K; kk += 8) {
        float4 av = *(const float4*)(Ap + kk);
        float4 wv = *(const float4*)(Wp + (size_t)kk * N);
        As[acol + 0][arow] = av.x;
        As[acol + 1][arow] = av.y;
        As[acol + 2][arow] = av.z;
        As[acol + 3][arow] = av.w;
        *(float4*)&Ws[wrow][wcol] = wv;
        __syncthreads();

#pragma unroll
        for (int k = 0; k < 8; k++) {
            float4 a0 = *(const float4*)&As[k][ty * 8];
            float4 a1 = *(const float4*)&As[k][ty * 8 + 4];
            float4 b0 = *(const float4*)&Ws[k][tx * 8];
            float4 b1 = *(const float4*)&Ws[k][tx * 8 + 4];
            float ra[8] = {a0.x, a0.y, a0.z, a0.w, a1.x, a1.y, a1.z, a1.w};
            float rb[8] = {b0.x, b0.y, b0.z, b0.w, b1.x, b1.y, b1.z, b1.w};
#pragma unroll
            for (int i = 0; i < 8; i++)
#pragma unroll
                for (int j = 0; j < 8; j++)
                    acc[i][j] += ra[i] * rb[j];
        }
        __syncthreads();
    }

#pragma unroll
    for (int i = 0; i < 8; i++) {
        const int row = bm + ty * 8 + i;
        float* crow = C + (size_t)row * N + bn + tx * 8;
#pragma unroll
        for (int j = 0; j < 8; j += 4) {
            float4 v;
            v.x = acc[i][j + 0];
            v.y = acc[i][j + 1];
            v.z = acc[i][j + 2];
            v.w = acc[i][j + 3];
            if (bias) {
                const int c0 = bn + tx * 8 + j;
                v.x += bias[c0 + 0];
                v.y += bias[c0 + 1];
                v.z += bias[c0 + 2];
                v.w += bias[c0 + 3];
            }
            *(float4*)(crow + j) = v;
        }
    }
}

// ---------------------------------------------------------------------------
// QK^T with scale + mask.  One block per (b,h).  S[(bh*Lq+q)*Lk + k].
// ---------------------------------------------------------------------------
__global__ void __launch_bounds__(256)
qk_kernel(const float* __restrict__ Q, const float* __restrict__ K,
          float* __restrict__ S,
          const int* __restrict__ qm, const int* __restrict__ km,
          int Lq, int Lk, float scale)
{
    __shared__ float Qs[96][33];
    __shared__ float Ks[96][33];

    const int bh = blockIdx.x;
    const int b  = bh >> 2;
    const int h  = bh & 3;
    const int tid = threadIdx.x;
    const int tx  = tid & 15;
    const int ty  = tid >> 4;

    float acc[6][6];
#pragma unroll
    for (int i = 0; i < 6; i++)
#pragma unroll
        for (int j = 0; j < 6; j++) acc[i][j] = 0.0f;

    for (int dd = 0; dd < DHv; dd += 32) {
        for (int idx = tid; idx < 96 * 32; idx += 256) {
            const int q = idx >> 5, d = idx & 31;
            Qs[q][d] = (q < Lq)
                ? Q[(size_t)(b * Lq + q) * Dv + h * DHv + dd + d] : 0.0f;
        }
        for (int idx = tid; idx < 96 * 32; idx += 256) {
            const int k = idx >> 5, d = idx & 31;
            Ks[k][d] = (k < Lk)
                ? K[(size_t)(b * Lk + k) * Dv + h * DHv + dd + d] : 0.0f;
        }
        __syncthreads();

#pragma unroll
        for (int d = 0; d < 32; d++) {
            float qa[6], kb[6];
#pragma unroll
            for (int i = 0; i < 6; i++) qa[i] = Qs[ty + 16 * i][d];
#pragma unroll
            for (int j = 0; j < 6; j++) kb[j] = Ks[tx + 16 * j][d];
#pragma unroll
            for (int i = 0; i < 6; i++)
#pragma unroll
                for (int j = 0; j < 6; j++)
                    acc[i][j] += qa[i] * kb[j];
        }
        __syncthreads();
    }

#pragma unroll
    for (int i = 0; i < 6; i++) {
        const int q = ty + 16 * i;
        if (q >= Lq) continue;
        const int qok = qm[b * Lq + q];
#pragma unroll
        for (int j = 0; j < 6; j++) {
            const int k = tx + 16 * j;
            if (k >= Lk) continue;
            const bool ok = (qok != 0) && (km[b * Lk + k] != 0);
            S[((size_t)bh * Lq + q) * Lk + k] = ok ? acc[i][j] * scale : NEGF;
        }
    }
}

// ---------------------------------------------------------------------------
// Row softmax with mask semantics: masked entries (==NEGF) -> 0; all-masked
// row -> all zeros.  One warp per row, 4 warps per block.
// ---------------------------------------------------------------------------
__global__ void __launch_bounds__(128)
softmax_kernel(float* __restrict__ S, int Lk)
{
    const int row = blockIdx.x * 4 + (threadIdx.x >> 5);
    const int l   = threadIdx.x & 31;
    float* s = S + (size_t)row * Lk;

    float v0 = (l      < Lk) ? s[l]      : -3.4e38f;
    float v1 = (l + 32 < Lk) ? s[l + 32] : -3.4e38f;
    float v2 = (l + 64 < Lk) ? s[l + 64] : -3.4e38f;

    float mx = fmaxf(v0, fmaxf(v1, v2));
#pragma unroll
    for (int o = 16; o; o >>= 1) mx = fmaxf(mx, __shfl_xor_sync(0xffffffffu, mx, o));

    float e0 = (l      < Lk && v0 != NEGF) ? __expf(v0 - mx) : 0.0f;
    float e1 = (l + 32 < Lk && v1 != NEGF) ? __expf(v1 - mx) : 0.0f;
    float e2 = (l + 64 < Lk && v2 != NEGF) ? __expf(v2 - mx) : 0.0f;

    float sum = e0 + e1 + e2;
#pragma unroll
    for (int o = 16; o; o >>= 1) sum += __shfl_xor_sync(0xffffffffu, sum, o);

    const float inv = (sum > 0.0f) ? (1.0f / sum) : 0.0f;
    if (l      < Lk) s[l]      = e0 * inv;
    if (l + 32 < Lk) s[l + 32] = e1 * inv;
    if (l + 64 < Lk) s[l + 64] = e2 * inv;
}

// ---------------------------------------------------------------------------
// AO[q, h*256 + dt*64 + dc] = sum_k S[q,k] * V[k, h*256 + dt*64 + dc]
// grid (B*H, 4 d-tiles of 64), 256 threads.
// ---------------------------------------------------------------------------
__global__ void __launch_bounds__(256)
av_kernel(const float* __restrict__ S, const float* __restrict__ V,
          float* __restrict__ AO, int Lq, int Lk)
{
    __shared__ float Ss[96][33];
    __shared__ float Vs[32][65];

    const int bh = blockIdx.x;
    const int b  = bh >> 2;
    const int h  = bh & 3;
    const int dt = blockIdx.y;          // 0..3
    const int tid = threadIdx.x;
    const int tx  = tid & 15;           // d direction (x4 of 16)
    const int ty  = tid >> 4;           // q direction (x6 of 16)

    float acc[6][4];
#pragma unroll
    for (int i = 0; i < 6; i++)
#pragma unroll
        for (int j = 0; j < 4; j++) acc[i][j] = 0.0f;

    for (int kk = 0; kk < Lk; kk += 32) {
        for (int idx = tid; idx < 96 * 32; idx += 256) {
            const int q = idx >> 5, k = idx & 31;
            Ss[q][k] = (q < Lq)
                ? S[((size_t)bh * Lq + q) * Lk + kk + k] : 0.0f;
        }
        for (int idx = tid; idx < 32 * 64; idx += 256) {
            const int kr = idx >> 6, dc = idx & 63;
            Vs[kr][dc] = V[(size_t)(b * Lk + kk + kr) * Dv + h * DHv + dt * 64 + dc];
        }
        __syncthreads();

#pragma unroll
        for (int k = 0; k < 32; k++) {
            float sa[6], vb[4];
#pragma unroll
            for (int i = 0; i < 6; i++) sa[i] = Ss[ty + 16 * i][k];
#pragma unroll
            for (int j = 0; j < 4; j++) vb[j] = Vs[k][tx + 16 * j];
#pragma unroll
            for (int i = 0; i < 6; i++)
#pragma unroll
                for (int j = 0; j < 4; j++)
                    acc[i][j] += sa[i] * vb[j];
        }
        __syncthreads();
    }

#pragma unroll
    for (int i = 0; i < 6; i++) {
        const int q = ty + 16 * i;
        if (q >= Lq) continue;
#pragma unroll
        for (int j = 0; j < 4; j++) {
            AO[(size_t)(b * Lq + q) * Dv + h * DHv + dt * 64 + tx + 16 * j] = acc[i][j];
        }
    }
}

// ---------------------------------------------------------------------------
// LayerNorm over last dim D=1024.  One block (256 threads) per row.
// ---------------------------------------------------------------------------
__global__ void __launch_bounds__(256)
ln_kernel(const float* __restrict__ X, const float* __restrict__ g,
          const float* __restrict__ b, float* __restrict__ Y)
{
    const int row = blockIdx.x;
    const int t   = threadIdx.x;
    const float4 v = ((const float4*)(X + (size_t)row * Dv))[t];

    float s  = v.x + v.y + v.z + v.w;
    float ss = v.x * v.x + v.y * v.y + v.z * v.z + v.w * v.w;

    __shared__ float shs[8], shq[8];
#pragma unroll
    for (int o = 16; o; o >>= 1) {
        s  += __shfl_xor_sync(0xffffffffu, s,  o);
        ss += __shfl_xor_sync(0xffffffffu, ss, o);
    }
    const int w = t >> 5, l = t & 31;
    if (l == 0) { shs[w] = s; shq[w] = ss; }
    __syncthreads();
    float m = 0.0f, q = 0.0f;
#pragma unroll
    for (int i = 0; i < 8; i++) { m += shs[i]; q += shq[i]; }
    m *= (1.0f / Dv);
    q  = q * (1.0f / Dv) - m * m;
    const float r = rsqrtf(q + 1e-3f);

    const float4 gv = ((const float4*)g)[t];
    const float4 bv = ((const float4*)b)[t];
    float4 o;
    o.x = (v.x - m) * r * gv.x + bv.x;
    o.y = (v.y - m) * r * gv.y + bv.y;
    o.z = (v.z - m) * r * gv.z + bv.z;
    o.w = (v.w - m) * r * gv.w + bv.w;
    ((float4*)(Y + (size_t)row * Dv))[t] = o;
}

// ---------------------------------------------------------------------------
// Host orchestration
// ---------------------------------------------------------------------------
static inline void gemm(const float* A, const float* W, const float* bias,
                        float* C, int M, int N, int K)
{
    dim3 grid(N / 128, M / 128);
    sgemm_kernel<<<grid, 256>>>(A, W, bias, C, M, N, K);
}

static inline void attention(const float* Q, const float* K, const float* V,
                             float* S, float* AO,
                             const int* qm, const int* km, int Lq, int Lk)
{
    qk_kernel<<<BHv, 256>>>(Q, K, S, qm, km, Lq, Lk, 0.0625f);  // 1/sqrt(256)
    softmax_kernel<<<BHv * Lq / 4, 128>>>(S, Lk);
    av_kernel<<<dim3(BHv, 4), 256>>>(S, V, AO, Lq, Lk);
}

extern "C" void kernel_launch(void* const* d_in, const int* in_sizes, int n_in,
                              void* d_out, int out_size)
{
    const float* text_emb  = (const float*)d_in[0];
    const float* image_emb = (const float*)d_in[1];
    const int*   text_mask  = (const int*)d_in[2];
    const int*   image_mask = (const int*)d_in[3];
    const float* W_tp = (const float*)d_in[4];
    const float* b_tp = (const float*)d_in[5];
    const float* W_ip = (const float*)d_in[6];
    const float* b_ip = (const float*)d_in[7];
    const float* ta_Wq = (const float*)d_in[8];
    const float* ta_Wk = (const float*)d_in[9];
    const float* ta_Wv = (const float*)d_in[10];
    const float* ta_Wo = (const float*)d_in[11];
    const float* ia_Wq = (const float*)d_in[12];
    const float* ia_Wk = (const float*)d_in[13];
    const float* ia_Wv = (const float*)d_in[14];
    const float* ia_Wo = (const float*)d_in[15];
    const float* ts_Wq = (const float*)d_in[16];
    const float* ts_Wk = (const float*)d_in[17];
    const float* ts_Wv = (const float*)d_in[18];
    const float* ts_Wo = (const float*)d_in[19];
    const float* is_Wq = (const float*)d_in[20];
    const float* is_Wk = (const float*)d_in[21];
    const float* is_Wv = (const float*)d_in[22];
    const float* is_Wo = (const float*)d_in[23];
    const float* ln_ta_g = (const float*)d_in[24];
    const float* ln_ta_b = (const float*)d_in[25];
    const float* ln_ia_g = (const float*)d_in[26];
    const float* ln_ia_b = (const float*)d_in[27];
    const float* ln_ts_g = (const float*)d_in[28];
    const float* ln_ts_b = (const float*)d_in[29];
    const float* ln_is_g = (const float*)d_in[30];
    const float* ln_is_b = (const float*)d_in[31];

    float* out_text = (float*)d_out;                                  // [128,64,1024]
    float* out_img  = (float*)d_out + (size_t)Bv * LIv * Dv;          // [128,96,1024]

    float *Pt, *Pi, *Q, *K, *V, *S, *AO, *Xt, *Xi;
    cudaGetSymbolAddress((void**)&Pt, g_Pt);
    cudaGetSymbolAddress((void**)&Pi, g_Pi);
    cudaGetSymbolAddress((void**)&Q,  g_Qb);
    cudaGetSymbolAddress((void**)&K,  g_Kb);
    cudaGetSymbolAddress((void**)&V,  g_Vb);
    cudaGetSymbolAddress((void**)&S,  g_Sb);
    cudaGetSymbolAddress((void**)&AO, g_AO);
    cudaGetSymbolAddress((void**)&Xt, g_Xt);
    cudaGetSymbolAddress((void**)&Xi, g_Xi);

    const int Mt = Bv * LTv;   // 12288 (text-length rows)
    const int Mi = Bv * LIv;   // 8192  (image-length rows)

    // Projections
    gemm(text_emb,  W_tp, b_tp, Pt, Mt, Dv, DTv);
    gemm(image_emb, W_ip, b_ip, Pi, Mi, Dv, DIv);

    // --- text cross-attn: q=image_proj, k=text_proj, v=raw text ---
    gemm(Pi,       ta_Wq, nullptr, Q, Mi, Dv, Dv);
    gemm(Pt,       ta_Wk, nullptr, K, Mt, Dv, Dv);
    gemm(text_emb, ta_Wv, nullptr, V, Mt, Dv, DTv);
    attention(Q, K, V, S, AO, image_mask, text_mask, LIv, LTv);
    gemm(AO, ta_Wo, nullptr, Q, Mi, Dv, Dv);
    ln_kernel<<<Mi, 256>>>(Q, ln_ta_g, ln_ta_b, Xt);

    // --- image cross-attn: q=text_proj, k=image_proj, v=raw image ---
    gemm(Pt,        ia_Wq, nullptr, Q, Mt, Dv, Dv);
    gemm(Pi,        ia_Wk, nullptr, K, Mi, Dv, Dv);
    gemm(image_emb, ia_Wv, nullptr, V, Mi, Dv, DIv);
    attention(Q, K, V, S, AO, text_mask, image_mask, LTv, LIv);
    gemm(AO, ia_Wo, nullptr, Q, Mt, Dv, Dv);
    ln_kernel<<<Mt, 256>>>(Q, ln_ia_g, ln_ia_b, Xi);

    // --- text self-attn (on Xt [B,LI,D], masks = image_mask) ---
    gemm(Xt, ts_Wq, nullptr, Q, Mi, Dv, Dv);
    gemm(Xt, ts_Wk, nullptr, K, Mi, Dv, Dv);
    gemm(Xt, ts_Wv, nullptr, V, Mi, Dv, Dv);
    attention(Q, K, V, S, AO, image_mask, image_mask, LIv, LIv);
    gemm(AO, ts_Wo, nullptr, Q, Mi, Dv, Dv);
    ln_kernel<<<Mi, 256>>>(Q, ln_ts_g, ln_ts_b, out_text);

    // --- image self-attn (on Xi [B,LT,D], masks = text_mask) ---
    gemm(Xi, is_Wq, nullptr, Q, Mt, Dv, Dv);
    gemm(Xi, is_Wk, nullptr, K, Mt, Dv, Dv);
    gemm(Xi, is_Wv, nullptr, V, Mt, Dv, Dv);
    attention(Q, K, V, S, AO, text_mask, text_mask, LTv, LTv);
    gemm(AO, is_Wo, nullptr, Q, Mt, Dv, Dv);
    ln_kernel<<<Mt, 256>>>(Q, ln_is_g, ln_is_b, out_img);
}

// round 3
// speedup vs baseline: 2.7528x; 2.7528x over previous
#include <cuda_runtime.h>
#include <cstdint>

// ---------------------------------------------------------------------------
// Problem dims
// ---------------------------------------------------------------------------
#define Bv   128
#define LTv  96
#define LIv  64
#define Dv   1024
#define Hv   4
#define DHv  256
#define DTv  1024
#define DIv  2048
#define BHv  (Bv * Hv)    // 512

#define NEGF (-2147483648.0f)   // -2^31

// ---------------------------------------------------------------------------
// Scratch buffers
// ---------------------------------------------------------------------------
static __device__ float g_Pt[(size_t)Bv * LTv * Dv];
static __device__ float g_Pi[(size_t)Bv * LIv * Dv];
static __device__ float g_Qb[(size_t)Bv * LTv * Dv];
static __device__ float g_Kb[(size_t)Bv * LTv * Dv];
static __device__ float g_Vb[(size_t)Bv * LTv * Dv];
static __device__ float g_Sb[(size_t)BHv * 96 * 96];
static __device__ float g_AO[(size_t)Bv * LTv * Dv];
static __device__ float g_Xt[(size_t)Bv * LIv * Dv];
static __device__ float g_Xi[(size_t)Bv * LTv * Dv];
// transposed (and tf32-rounded) weights: 16 x [1024,1024] + 2 x [1024,2048]
static __device__ float g_Wt[(size_t)16 * 1024 * 1024 + (size_t)2 * 1024 * 2048];

// ---------------------------------------------------------------------------
// PTX helpers
// ---------------------------------------------------------------------------
__device__ __forceinline__ uint32_t smem_u32(const void* p) {
    uint32_t a;
    asm("{ .reg .u64 t; cvta.to.shared.u64 t, %1; cvt.u32.u64 %0, t; }" : "=r"(a) : "l"(p));
    return a;
}
#define CP_COMMIT() asm volatile("cp.async.commit_group;" ::: "memory")
#define CP_WAIT1()  asm volatile("cp.async.wait_group 1;" ::: "memory")
#define CP_WAIT0()  asm volatile("cp.async.wait_group 0;" ::: "memory")

__device__ __forceinline__ void cp16(uint32_t dst, const float* src) {
    asm volatile("cp.async.cg.shared.global [%0], [%1], 16;" :: "r"(dst), "l"(src));
}
__device__ __forceinline__ uint32_t f2tf32(float v) {
    uint32_t u;
    asm("cvt.rna.tf32.f32 %0, %1;" : "=r"(u) : "f"(v));
    return u;
}
__device__ __forceinline__ void mma_tf32(float* c, uint32_t a0, uint32_t a1,
                                         uint32_t a2, uint32_t a3,
                                         uint32_t b0, uint32_t b1) {
    asm volatile(
        "mma.sync.aligned.m16n8k8.row.col.f32.tf32.tf32.f32 "
        "{%0,%1,%2,%3}, {%4,%5,%6,%7}, {%8,%9}, {%0,%1,%2,%3};"
        : "+f"(c[0]), "+f"(c[1]), "+f"(c[2]), "+f"(c[3])
        : "r"(a0), "r"(a1), "r"(a2), "r"(a3), "r"(b0), "r"(b1));
}

// swizzled index into a [rows][32-float] tile (float units)
__device__ __forceinline__ int swz(int r, int c) {
    return r * 32 + ((((c >> 2) ^ (r & 7)) << 2) | (c & 3));
}

// ---------------------------------------------------------------------------
// mma.sync tf32 GEMM: C[M,1024] = A[M,K] @ W[K,1024] (+bias)
// A row-major [M,K] (fp32, cvt in-kernel); Wt row-major [1024,K] tf32-rounded.
// CTA 128x128, 8 warps (2m x 4n), warp tile 64x32, K-chunk 32, 2-stage cp.async.
// ---------------------------------------------------------------------------
#define GN 1024
#define STAGE_FLOATS 8192            // A 4096 + B 4096
#define SMEM_BYTES   (2 * STAGE_FLOATS * 4)   // 65536

__device__ __forceinline__ void load_chunk(uint32_t sb, int s,
                                           const float* __restrict__ A,
                                           const float* __restrict__ Wt,
                                           int K, int kk, int bm, int bn, int tid)
{
    const uint32_t uA = sb + s * (STAGE_FLOATS * 4);
    const uint32_t uB = uA + 16384u;
#pragma unroll
    for (int j = 0; j < 4; j++) {               // A: 128 rows x 128B
        int idx = tid + 256 * j;
        int row = idx >> 3, seg = idx & 7;
        cp16(uA + row * 128 + ((seg ^ (row & 7)) << 4),
             A + (size_t)(bm + row) * K + kk + seg * 4);
    }
#pragma unroll
    for (int j = 0; j < 4; j++) {               // B: 128 rows (n) x 128B
        int idx = tid + 256 * j;
        int row = idx >> 3, seg = idx & 7;
        cp16(uB + row * 128 + ((seg ^ (row & 7)) << 4),
             Wt + (size_t)(bn + row) * K + kk + seg * 4);
    }
    CP_COMMIT();
}

__global__ void __launch_bounds__(256, 2)
mma_gemm_kernel(const float* __restrict__ A, const float* __restrict__ Wt,
                const float* __restrict__ bias, float* __restrict__ C,
                int M, int K)
{
    extern __shared__ float smf[];
    const uint32_t sb = smem_u32(smf);
    const int tid  = threadIdx.x;
    const int lane = tid & 31;
    const int warp = tid >> 5;
    const int wm   = warp >> 2;        // 0..1 -> m offset 0/64
    const int wn   = warp & 3;         // 0..3 -> n offset 0/32/64/96
    const int bm   = blockIdx.y * 128;
    const int bn   = blockIdx.x * 128;

    const int qr = lane >> 2;          // 0..7
    const int qc = lane & 3;           // 0..3

    float acc[4][4][4];
#pragma unroll
    for (int mi = 0; mi < 4; mi++)
#pragma unroll
        for (int ni = 0; ni < 4; ni++)
#pragma unroll
            for (int r = 0; r < 4; r++) acc[mi][ni][r] = 0.0f;

    const int NC = K >> 5;
    load_chunk(sb, 0, A, Wt, K, 0,  bm, bn, tid);
    load_chunk(sb, 1, A, Wt, K, 32, bm, bn, tid);

    for (int i = 0; i < NC; i++) {
        const int s = i & 1;
        if (i < NC - 1) CP_WAIT1(); else CP_WAIT0();
        __syncthreads();

        const float* As = smf + s * STAGE_FLOATS;
        const float* Bs = As + 4096;

#pragma unroll
        for (int ks = 0; ks < 4; ks++) {
            const int k0 = ks * 8;
            // B fragments: Bs[n][k], n = wn*32 + ni*8 + qr, k = k0+qc / +4
            uint32_t bf[4][2];
#pragma unroll
            for (int ni = 0; ni < 4; ni++) {
                const int r = wn * 32 + ni * 8 + qr;
                bf[ni][0] = __float_as_uint(Bs[swz(r, k0 + qc)]);
                bf[ni][1] = __float_as_uint(Bs[swz(r, k0 + qc + 4)]);
            }
#pragma unroll
            for (int mi = 0; mi < 4; mi++) {
                const int r0 = wm * 64 + mi * 16 + qr;
                const uint32_t a0 = f2tf32(As[swz(r0,     k0 + qc)]);
                const uint32_t a1 = f2tf32(As[swz(r0 + 8, k0 + qc)]);
                const uint32_t a2 = f2tf32(As[swz(r0,     k0 + qc + 4)]);
                const uint32_t a3 = f2tf32(As[swz(r0 + 8, k0 + qc + 4)]);
#pragma unroll
                for (int ni = 0; ni < 4; ni++)
                    mma_tf32(acc[mi][ni], a0, a1, a2, a3, bf[ni][0], bf[ni][1]);
            }
        }
        __syncthreads();
        if (i + 2 < NC) load_chunk(sb, s, A, Wt, K, (i + 2) * 32, bm, bn, tid);
    }

    // Epilogue: c0 (row, col), c1 (row, col+1), c2 (row+8, col), c3 (row+8, col+1)
#pragma unroll
    for (int mi = 0; mi < 4; mi++) {
        const int row = bm + wm * 64 + mi * 16 + qr;
#pragma unroll
        for (int ni = 0; ni < 4; ni++) {
            const int col = bn + wn * 32 + ni * 8 + qc * 2;
            float2 v0 = make_float2(acc[mi][ni][0], acc[mi][ni][1]);
            float2 v1 = make_float2(acc[mi][ni][2], acc[mi][ni][3]);
            if (bias) {
                const float2 bz = *(const float2*)(bias + col);
                v0.x += bz.x; v0.y += bz.y;
                v1.x += bz.x; v1.y += bz.y;
            }
            *(float2*)(C + (size_t)row * GN + col)       = v0;
            *(float2*)(C + (size_t)(row + 8) * GN + col) = v1;
        }
    }
}

// ---------------------------------------------------------------------------
// Batched weight transpose + tf32 rounding: dst[n][k] = tf32(src[k][n])
// ---------------------------------------------------------------------------
struct SrcArr16 { const float* p[16]; };
struct SrcArr2  { const float* p[2]; };

template <typename SA>
__global__ void __launch_bounds__(256)
transpose_kernel(SA srcs, float* __restrict__ dstbase, int K, size_t dst_stride)
{
    __shared__ float t[32][33];
    const float* src = srcs.p[blockIdx.z];
    float* dst = dstbase + (size_t)blockIdx.z * dst_stride;
    const int n0 = blockIdx.x * 32, k0 = blockIdx.y * 32;
    const int tx = threadIdx.x, ty = threadIdx.y;
#pragma unroll
    for (int j = 0; j < 32; j += 8)
        t[ty + j][tx] = src[(size_t)(k0 + ty + j) * GN + n0 + tx];
    __syncthreads();
#pragma unroll
    for (int j = 0; j < 32; j += 8)
        dst[(size_t)(n0 + ty + j) * K + k0 + tx] =
            __uint_as_float(f2tf32(t[tx][ty + j]));
}

// ---------------------------------------------------------------------------
// Attention kernels (unchanged from R1 -- known good)
// ---------------------------------------------------------------------------
__global__ void __launch_bounds__(256)
qk_kernel(const float* __restrict__ Q, const float* __restrict__ K,
          float* __restrict__ S,
          const int* __restrict__ qm, const int* __restrict__ km,
          int Lq, int Lk, float scale)
{
    __shared__ float Qs[96][33];
    __shared__ float Ks[96][33];

    const int bh = blockIdx.x;
    const int b  = bh >> 2;
    const int h  = bh & 3;
    const int tid = threadIdx.x;
    const int tx  = tid & 15;
    const int ty  = tid >> 4;

    float acc[6][6];
#pragma unroll
    for (int i = 0; i < 6; i++)
#pragma unroll
        for (int j = 0; j < 6; j++) acc[i][j] = 0.0f;

    for (int dd = 0; dd < DHv; dd += 32) {
        for (int idx = tid; idx < 96 * 32; idx += 256) {
            const int q = idx >> 5, d = idx & 31;
            Qs[q][d] = (q < Lq) ? Q[(size_t)(b * Lq + q) * Dv + h * DHv + dd + d] : 0.0f;
        }
        for (int idx = tid; idx < 96 * 32; idx += 256) {
            const int k = idx >> 5, d = idx & 31;
            Ks[k][d] = (k < Lk) ? K[(size_t)(b * Lk + k) * Dv + h * DHv + dd + d] : 0.0f;
        }
        __syncthreads();

#pragma unroll
        for (int d = 0; d < 32; d++) {
            float qa[6], kb[6];
#pragma unroll
            for (int i = 0; i < 6; i++) qa[i] = Qs[ty + 16 * i][d];
#pragma unroll
            for (int j = 0; j < 6; j++) kb[j] = Ks[tx + 16 * j][d];
#pragma unroll
            for (int i = 0; i < 6; i++)
#pragma unroll
                for (int j = 0; j < 6; j++)
                    acc[i][j] += qa[i] * kb[j];
        }
        __syncthreads();
    }

#pragma unroll
    for (int i = 0; i < 6; i++) {
        const int q = ty + 16 * i;
        if (q >= Lq) continue;
        const int qok = qm[b * Lq + q];
#pragma unroll
        for (int j = 0; j < 6; j++) {
            const int k = tx + 16 * j;
            if (k >= Lk) continue;
            const bool ok = (qok != 0) && (km[b * Lk + k] != 0);
            S[((size_t)bh * Lq + q) * Lk + k] = ok ? acc[i][j] * scale : NEGF;
        }
    }
}

__global__ void __launch_bounds__(128)
softmax_kernel(float* __restrict__ S, int Lk)
{
    const int row = blockIdx.x * 4 + (threadIdx.x >> 5);
    const int l   = threadIdx.x & 31;
    float* s = S + (size_t)row * Lk;

    float v0 = (l      < Lk) ? s[l]      : -3.4e38f;
    float v1 = (l + 32 < Lk) ? s[l + 32] : -3.4e38f;
    float v2 = (l + 64 < Lk) ? s[l + 64] : -3.4e38f;

    float mx = fmaxf(v0, fmaxf(v1, v2));
#pragma unroll
    for (int o = 16; o; o >>= 1) mx = fmaxf(mx, __shfl_xor_sync(0xffffffffu, mx, o));

    float e0 = (l      < Lk && v0 != NEGF) ? __expf(v0 - mx) : 0.0f;
    float e1 = (l + 32 < Lk && v1 != NEGF) ? __expf(v1 - mx) : 0.0f;
    float e2 = (l + 64 < Lk && v2 != NEGF) ? __expf(v2 - mx) : 0.0f;

    float sum = e0 + e1 + e2;
#pragma unroll
    for (int o = 16; o; o >>= 1) sum += __shfl_xor_sync(0xffffffffu, sum, o);

    const float inv = (sum > 0.0f) ? (1.0f / sum) : 0.0f;
    if (l      < Lk) s[l]      = e0 * inv;
    if (l + 32 < Lk) s[l + 32] = e1 * inv;
    if (l + 64 < Lk) s[l + 64] = e2 * inv;
}

__global__ void __launch_bounds__(256)
av_kernel(const float* __restrict__ S, const float* __restrict__ V,
          float* __restrict__ AO, int Lq, int Lk)
{
    __shared__ float Ss[96][33];
    __shared__ float Vs[32][65];

    const int bh = blockIdx.x;
    const int b  = bh >> 2;
    const int h  = bh & 3;
    const int dt = blockIdx.y;
    const int tid = threadIdx.x;
    const int tx  = tid & 15;
    const int ty  = tid >> 4;

    float acc[6][4];
#pragma unroll
    for (int i = 0; i < 6; i++)
#pragma unroll
        for (int j = 0; j < 4; j++) acc[i][j] = 0.0f;

    for (int kk = 0; kk < Lk; kk += 32) {
        for (int idx = tid; idx < 96 * 32; idx += 256) {
            const int q = idx >> 5, k = idx & 31;
            Ss[q][k] = (q < Lq) ? S[((size_t)bh * Lq + q) * Lk + kk + k] : 0.0f;
        }
        for (int idx = tid; idx < 32 * 64; idx += 256) {
            const int kr = idx >> 6, dc = idx & 63;
            Vs[kr][dc] = V[(size_t)(b * Lk + kk + kr) * Dv + h * DHv + dt * 64 + dc];
        }
        __syncthreads();

#pragma unroll
        for (int k = 0; k < 32; k++) {
            float sa[6], vb[4];
#pragma unroll
            for (int i = 0; i < 6; i++) sa[i] = Ss[ty + 16 * i][k];
#pragma unroll
            for (int j = 0; j < 4; j++) vb[j] = Vs[k][tx + 16 * j];
#pragma unroll
            for (int i = 0; i < 6; i++)
#pragma unroll
                for (int j = 0; j < 4; j++)
                    acc[i][j] += sa[i] * vb[j];
        }
        __syncthreads();
    }

#pragma unroll
    for (int i = 0; i < 6; i++) {
        const int q = ty + 16 * i;
        if (q >= Lq) continue;
#pragma unroll
        for (int j = 0; j < 4; j++) {
            AO[(size_t)(b * Lq + q) * Dv + h * DHv + dt * 64 + tx + 16 * j] = acc[i][j];
        }
    }
}

__global__ void __launch_bounds__(256)
ln_kernel(const float* __restrict__ X, const float* __restrict__ g,
          const float* __restrict__ b, float* __restrict__ Y)
{
    const int row = blockIdx.x;
    const int t   = threadIdx.x;
    const float4 v = ((const float4*)(X + (size_t)row * Dv))[t];

    float s  = v.x + v.y + v.z + v.w;
    float ss = v.x * v.x + v.y * v.y + v.z * v.z + v.w * v.w;

    __shared__ float shs[8], shq[8];
#pragma unroll
    for (int o = 16; o; o >>= 1) {
        s  += __shfl_xor_sync(0xffffffffu, s,  o);
        ss += __shfl_xor_sync(0xffffffffu, ss, o);
    }
    const int w = t >> 5, l = t & 31;
    if (l == 0) { shs[w] = s; shq[w] = ss; }
    __syncthreads();
    float m = 0.0f, q = 0.0f;
#pragma unroll
    for (int i = 0; i < 8; i++) { m += shs[i]; q += shq[i]; }
    m *= (1.0f / Dv);
    q  = q * (1.0f / Dv) - m * m;
    const float r = rsqrtf(q + 1e-3f);

    const float4 gv = ((const float4*)g)[t];
    const float4 bv = ((const float4*)b)[t];
    float4 o;
    o.x = (v.x - m) * r * gv.x + bv.x;
    o.y = (v.y - m) * r * gv.y + bv.y;
    o.z = (v.z - m) * r * gv.z + bv.z;
    o.w = (v.w - m) * r * gv.w + bv.w;
    ((float4*)(Y + (size_t)row * Dv))[t] = o;
}

// ---------------------------------------------------------------------------
// Host orchestration
// ---------------------------------------------------------------------------
static inline void gemm(const float* A, const float* Wt, const float* bias,
                        float* C, int M, int K)
{
    dim3 grid(GN / 128, M / 128);
    mma_gemm_kernel<<<grid, 256, SMEM_BYTES>>>(A, Wt, bias, C, M, K);
}

static inline void attention(const float* Q, const float* K, const float* V,
                             float* S, float* AO,
                             const int* qm, const int* km, int Lq, int Lk)
{
    qk_kernel<<<BHv, 256>>>(Q, K, S, qm, km, Lq, Lk, 0.0625f);
    softmax_kernel<<<BHv * Lq / 4, 128>>>(S, Lk);
    av_kernel<<<dim3(BHv, 4), 256>>>(S, V, AO, Lq, Lk);
}

extern "C" void kernel_launch(void* const* d_in, const int* in_sizes, int n_in,
                              void* d_out, int out_size)
{
    const float* text_emb  = (const float*)d_in[0];
    const float* image_emb = (const float*)d_in[1];
    const int*   text_mask  = (const int*)d_in[2];
    const int*   image_mask = (const int*)d_in[3];
    const float* W_tp = (const float*)d_in[4];
    const float* b_tp = (const float*)d_in[5];
    const float* W_ip = (const float*)d_in[6];
    const float* b_ip = (const float*)d_in[7];
    const float* ta_Wq = (const float*)d_in[8];
    const float* ta_Wk = (const float*)d_in[9];
    const float* ta_Wv = (const float*)d_in[10];
    const float* ta_Wo = (const float*)d_in[11];
    const float* ia_Wq = (const float*)d_in[12];
    const float* ia_Wk = (const float*)d_in[13];
    const float* ia_Wv = (const float*)d_in[14];
    const float* ia_Wo = (const float*)d_in[15];
    const float* ts_Wq = (const float*)d_in[16];
    const float* ts_Wk = (const float*)d_in[17];
    const float* ts_Wv = (const float*)d_in[18];
    const float* ts_Wo = (const float*)d_in[19];
    const float* is_Wq = (const float*)d_in[20];
    const float* is_Wk = (const float*)d_in[21];
    const float* is_Wv = (const float*)d_in[22];
    const float* is_Wo = (const float*)d_in[23];
    const float* ln_ta_g = (const float*)d_in[24];
    const float* ln_ta_b = (const float*)d_in[25];
    const float* ln_ia_g = (const float*)d_in[26];
    const float* ln_ia_b = (const float*)d_in[27];
    const float* ln_ts_g = (const float*)d_in[28];
    const float* ln_ts_b = (const float*)d_in[29];
    const float* ln_is_g = (const float*)d_in[30];
    const float* ln_is_b = (const float*)d_in[31];

    float* out_text = (float*)d_out;
    float* out_img  = (float*)d_out + (size_t)Bv * LIv * Dv;

    float *Pt, *Pi, *Q, *K, *V, *S, *AO, *Xt, *Xi, *Wt;
    cudaGetSymbolAddress((void**)&Pt, g_Pt);
    cudaGetSymbolAddress((void**)&Pi, g_Pi);
    cudaGetSymbolAddress((void**)&Q,  g_Qb);
    cudaGetSymbolAddress((void**)&K,  g_Kb);
    cudaGetSymbolAddress((void**)&V,  g_Vb);
    cudaGetSymbolAddress((void**)&S,  g_Sb);
    cudaGetSymbolAddress((void**)&AO, g_AO);
    cudaGetSymbolAddress((void**)&Xt, g_Xt);
    cudaGetSymbolAddress((void**)&Xi, g_Xi);
    cudaGetSymbolAddress((void**)&Wt, g_Wt);

    static int smem_set = 0;
    if (!smem_set) {
        cudaFuncSetAttribute(mma_gemm_kernel,
                             cudaFuncAttributeMaxDynamicSharedMemorySize, SMEM_BYTES);
        smem_set = 1;
    }

    // ---- transpose + tf32-round all weights ----
    SrcArr16 s16;
    s16.p[0]  = W_tp;  s16.p[1]  = ta_Wq; s16.p[2]  = ta_Wk; s16.p[3]  = ta_Wv;
    s16.p[4]  = ta_Wo; s16.p[5]  = ia_Wq; s16.p[6]  = ia_Wk; s16.p[7]  = ia_Wo;
    s16.p[8]  = ts_Wq; s16.p[9]  = ts_Wk; s16.p[10] = ts_Wv; s16.p[11] = ts_Wo;
    s16.p[12] = is_Wq; s16.p[13] = is_Wk; s16.p[14] = is_Wv; s16.p[15] = is_Wo;
    transpose_kernel<SrcArr16><<<dim3(32, 32, 16), dim3(32, 8)>>>(s16, Wt, 1024, 1 << 20);

    float* Wt2 = Wt + ((size_t)16 << 20);
    SrcArr2 s2;
    s2.p[0] = W_ip; s2.p[1] = ia_Wv;
    transpose_kernel<SrcArr2><<<dim3(32, 64, 2), dim3(32, 8)>>>(s2, Wt2, 2048, 1 << 21);

    #define WT(i)  (Wt + ((size_t)(i) << 20))
    const float* tW_tp  = WT(0);
    const float* tta_Wq = WT(1);  const float* tta_Wk = WT(2);
    const float* tta_Wv = WT(3);  const float* tta_Wo = WT(4);
    const float* tia_Wq = WT(5);  const float* tia_Wk = WT(6);
    const float* tia_Wo = WT(7);
    const float* tts_Wq = WT(8);  const float* tts_Wk = WT(9);
    const float* tts_Wv = WT(10); const float* tts_Wo = WT(11);
    const float* tis_Wq = WT(12); const float* tis_Wk = WT(13);
    const float* tis_Wv = WT(14); const float* tis_Wo = WT(15);
    const float* tW_ip  = Wt2;
    const float* tia_Wv = Wt2 + ((size_t)1 << 21);

    const int Mt = Bv * LTv;   // 12288
    const int Mi = Bv * LIv;   // 8192

    // Projections
    gemm(text_emb,  tW_tp, b_tp, Pt, Mt, 1024);
    gemm(image_emb, tW_ip, b_ip, Pi, Mi, 2048);

    // --- text cross-attn: q=image_proj, k=text_proj, v=raw text ---
    gemm(Pi,       tta_Wq, nullptr, Q, Mi, 1024);
    gemm(Pt,       tta_Wk, nullptr, K, Mt, 1024);
    gemm(text_emb, tta_Wv, nullptr, V, Mt, 1024);
    attention(Q, K, V, S, AO, image_mask, text_mask, LIv, LTv);
    gemm(AO, tta_Wo, nullptr, Q, Mi, 1024);
    ln_kernel<<<Mi, 256>>>(Q, ln_ta_g, ln_ta_b, Xt);

    // --- image cross-attn: q=text_proj, k=image_proj, v=raw image ---
    gemm(Pt,        tia_Wq, nullptr, Q, Mt, 1024);
    gemm(Pi,        tia_Wk, nullptr, K, Mi, 1024);
    gemm(image_emb, tia_Wv, nullptr, V, Mi, 2048);
    attention(Q, K, V, S, AO, text_mask, image_mask, LTv, LIv);
    gemm(AO, tia_Wo, nullptr, Q, Mt, 1024);
    ln_kernel<<<Mt, 256>>>(Q, ln_ia_g, ln_ia_b, Xi);

    // --- text self-attn (on Xt [B,LI,D], masks = image_mask) ---
    gemm(Xt, tts_Wq, nullptr, Q, Mi, 1024);
    gemm(Xt, tts_Wk, nullptr, K, Mi, 1024);
    gemm(Xt, tts_Wv, nullptr, V, Mi, 1024);
    attention(Q, K, V, S, AO, image_mask, image_mask, LIv, LIv);
    gemm(AO, tts_Wo, nullptr, Q, Mi, 1024);
    ln_kernel<<<Mi, 256>>>(Q, ln_ts_g, ln_ts_b, out_text);

    // --- image self-attn (on Xi [B,LT,D], masks = text_mask) ---
    gemm(Xi, tis_Wq, nullptr, Q, Mt, 1024);
    gemm(Xi, tis_Wk, nullptr, K, Mt, 1024);
    gemm(Xi, tis_Wv, nullptr, V, Mt, 1024);
    attention(Q, K, V, S, AO, text_mask, text_mask, LTv, LTv);
    gemm(AO, tis_Wo, nullptr, Q, Mt, 1024);
    ln_kernel<<<Mt, 256>>>(Q, ln_is_g, ln_is_b, out_img);
}

// round 4
// speedup vs baseline: 4.9988x; 1.8159x over previous
#include <cuda_runtime.h>
#include <cuda_fp16.h>
#include <cstdint>

// ---------------------------------------------------------------------------
// Problem dims
// ---------------------------------------------------------------------------
#define Bv   128
#define LTv  96
#define LIv  64
#define Dv   1024
#define Hv   4
#define DHv  256
#define DTv  1024
#define DIv  2048
#define BHv  (Bv * Hv)    // 512

#define NEGF (-2147483648.0f)   // -2^31

// ---------------------------------------------------------------------------
// Scratch buffers
// ---------------------------------------------------------------------------
static __device__ float g_Pt[(size_t)Bv * LTv * Dv];
static __device__ float g_Pi[(size_t)Bv * LIv * Dv];
static __device__ float g_Qb[(size_t)Bv * LTv * Dv];
static __device__ float g_Kb[(size_t)Bv * LTv * Dv];
static __device__ float g_Vb[(size_t)Bv * LTv * Dv];
static __device__ float g_Sb[(size_t)BHv * 96 * 96];
static __device__ float g_Xt[(size_t)Bv * LIv * Dv];
static __device__ float g_Xi[(size_t)Bv * LTv * Dv];
// fp16 twins
static __device__ __half g_tE16[(size_t)Bv * LTv * DTv];
static __device__ __half g_iE16[(size_t)Bv * LIv * DIv];
static __device__ __half g_Pt16[(size_t)Bv * LTv * Dv];
static __device__ __half g_Pi16[(size_t)Bv * LIv * Dv];
static __device__ __half g_AO16[(size_t)Bv * LTv * Dv];
static __device__ __half g_Xt16[(size_t)Bv * LIv * Dv];
static __device__ __half g_Xi16[(size_t)Bv * LTv * Dv];
// transposed fp16 weights: 16 x [1024,1024] + 2 x [1024,2048]
static __device__ __half g_Wh[(size_t)16 * 1024 * 1024 + (size_t)2 * 1024 * 2048];

// ---------------------------------------------------------------------------
// PTX helpers
// ---------------------------------------------------------------------------
__device__ __forceinline__ uint32_t smem_u32(const void* p) {
    uint32_t a;
    asm("{ .reg .u64 t; cvta.to.shared.u64 t, %1; cvt.u32.u64 %0, t; }" : "=r"(a) : "l"(p));
    return a;
}
#define CP_COMMIT() asm volatile("cp.async.commit_group;" ::: "memory")
#define CP_WAIT1()  asm volatile("cp.async.wait_group 1;" ::: "memory")
#define CP_WAIT0()  asm volatile("cp.async.wait_group 0;" ::: "memory")

__device__ __forceinline__ void cp16(uint32_t dst, const void* src) {
    asm volatile("cp.async.cg.shared.global [%0], [%1], 16;" :: "r"(dst), "l"(src));
}
__device__ __forceinline__ void ldsm4(uint32_t& r0, uint32_t& r1, uint32_t& r2,
                                      uint32_t& r3, uint32_t addr) {
    asm volatile("ldmatrix.sync.aligned.m8n8.x4.shared.b16 {%0,%1,%2,%3}, [%4];"
                 : "=r"(r0), "=r"(r1), "=r"(r2), "=r"(r3) : "r"(addr));
}
__device__ __forceinline__ void mma_f16(float* c, uint32_t a0, uint32_t a1,
                                        uint32_t a2, uint32_t a3,
                                        uint32_t b0, uint32_t b1) {
    asm volatile(
        "mma.sync.aligned.m16n8k16.row.col.f32.f16.f16.f32 "
        "{%0,%1,%2,%3}, {%4,%5,%6,%7}, {%8,%9}, {%0,%1,%2,%3};"
        : "+f"(c[0]), "+f"(c[1]), "+f"(c[2]), "+f"(c[3])
        : "r"(a0), "r"(a1), "r"(a2), "r"(a3), "r"(b0), "r"(b1));
}

// ---------------------------------------------------------------------------
// fp16 mma GEMM: C[M,1024] = A16[M,K] @ W[K,1024] (+bias), optional fp16 copy.
// A16 row-major [M,K]; Wh row-major [1024,K] (W transposed, fp16).
// CTA 128x128, 8 warps (2m x 4n), warp tile 64x32, BK=64, 2-stage cp.async.
// ---------------------------------------------------------------------------
#define GN 1024
#define STAGE_BYTES 32768u                     // A 16KB + B 16KB
#define SMEM_BYTES  (2 * STAGE_BYTES)          // 64KB

__device__ __forceinline__ void load_chunk_h(uint32_t sb, int s,
                                             const __half* __restrict__ A,
                                             const __half* __restrict__ Wt,
                                             int K, int kk, int bm, int bn, int tid)
{
    const uint32_t uA = sb + s * STAGE_BYTES;
    const uint32_t uB = uA + 16384u;
#pragma unroll
    for (int j = 0; j < 4; j++) {               // A: 128 rows x 128B (64 fp16)
        int idx = tid + 256 * j;
        int row = idx >> 3, seg = idx & 7;
        cp16(uA + row * 128 + ((seg ^ (row & 7)) << 4),
             A + (size_t)(bm + row) * K + kk + seg * 8);
    }
#pragma unroll
    for (int j = 0; j < 4; j++) {               // B: 128 n-rows x 128B
        int idx = tid + 256 * j;
        int row = idx >> 3, seg = idx & 7;
        cp16(uB + row * 128 + ((seg ^ (row & 7)) << 4),
             Wt + (size_t)(bn + row) * K + kk + seg * 8);
    }
    CP_COMMIT();
}

__global__ void __launch_bounds__(256, 2)
hgemm_kernel(const __half* __restrict__ A, const __half* __restrict__ Wt,
             const float* __restrict__ bias, float* __restrict__ C,
             __half* __restrict__ C16, int M, int K)
{
    extern __shared__ char smc[];
    const uint32_t sb = smem_u32(smc);
    const int tid  = threadIdx.x;
    const int lane = tid & 31;
    const int warp = tid >> 5;
    const int wm   = warp >> 2;        // 0..1 -> m offset 0/64
    const int wn   = warp & 3;         // 0..3 -> n offset 0/32/64/96
    const int bm   = blockIdx.y * 128;
    const int bn   = blockIdx.x * 128;

    const int lane15 = lane & 15;
    const int hi     = lane >> 4;      // 0/1 -> 8-col group

    int arow[4], brow[2];
#pragma unroll
    for (int mi = 0; mi < 4; mi++) arow[mi] = wm * 64 + mi * 16 + lane15;
#pragma unroll
    for (int nb = 0; nb < 2; nb++) brow[nb] = wn * 32 + nb * 16 + lane15;

    float acc[4][4][4];
#pragma unroll
    for (int mi = 0; mi < 4; mi++)
#pragma unroll
        for (int ni = 0; ni < 4; ni++)
#pragma unroll
            for (int r = 0; r < 4; r++) acc[mi][ni][r] = 0.0f;

    const int NC = K >> 6;
    load_chunk_h(sb, 0, A, Wt, K, 0,  bm, bn, tid);
    load_chunk_h(sb, 1, A, Wt, K, 64, bm, bn, tid);

    for (int i = 0; i < NC; i++) {
        const int s = i & 1;
        if (i < NC - 1) CP_WAIT1(); else CP_WAIT0();
        __syncthreads();

        const uint32_t uA = sb + s * STAGE_BYTES;
        const uint32_t uB = uA + 16384u;

#pragma unroll
        for (int ks = 0; ks < 4; ks++) {
            const int sg = ks * 2 + hi;            // 16B segment pre-xor
            uint32_t bf[4][2];
#pragma unroll
            for (int nb = 0; nb < 2; nb++) {
                uint32_t r0, r1, r2, r3;
                ldsm4(r0, r1, r2, r3,
                      uB + brow[nb] * 128 + ((sg ^ (brow[nb] & 7)) << 4));
                bf[nb * 2][0]     = r0; bf[nb * 2][1]     = r2;
                bf[nb * 2 + 1][0] = r1; bf[nb * 2 + 1][1] = r3;
            }
#pragma unroll
            for (int mi = 0; mi < 4; mi++) {
                uint32_t a0, a1, a2, a3;
                ldsm4(a0, a1, a2, a3,
                      uA + arow[mi] * 128 + ((sg ^ (arow[mi] & 7)) << 4));
#pragma unroll
                for (int ni = 0; ni < 4; ni++)
                    mma_f16(acc[mi][ni], a0, a1, a2, a3, bf[ni][0], bf[ni][1]);
            }
        }
        __syncthreads();
        if (i + 2 < NC) load_chunk_h(sb, s, A, Wt, K, (i + 2) * 64, bm, bn, tid);
    }

    const int qr = lane >> 2, qc = lane & 3;
#pragma unroll
    for (int mi = 0; mi < 4; mi++) {
        const int row = bm + wm * 64 + mi * 16 + qr;
#pragma unroll
        for (int ni = 0; ni < 4; ni++) {
            const int col = bn + wn * 32 + ni * 8 + qc * 2;
            float2 v0 = make_float2(acc[mi][ni][0], acc[mi][ni][1]);
            float2 v1 = make_float2(acc[mi][ni][2], acc[mi][ni][3]);
            if (bias) {
                const float2 bz = *(const float2*)(bias + col);
                v0.x += bz.x; v0.y += bz.y;
                v1.x += bz.x; v1.y += bz.y;
            }
            *(float2*)(C + (size_t)row * GN + col)       = v0;
            *(float2*)(C + (size_t)(row + 8) * GN + col) = v1;
            if (C16) {
                __half2 h0 = __floats2half2_rn(v0.x, v0.y);
                __half2 h1 = __floats2half2_rn(v1.x, v1.y);
                *(__half2*)(C16 + (size_t)row * GN + col)       = h0;
                *(__half2*)(C16 + (size_t)(row + 8) * GN + col) = h1;
            }
        }
    }
}

// ---------------------------------------------------------------------------
// fp32 -> fp16 convert
// ---------------------------------------------------------------------------
__global__ void __launch_bounds__(256)
f2h_kernel(const float4* __restrict__ src, uint2* __restrict__ dst, int n4)
{
    const int i = blockIdx.x * 256 + threadIdx.x;
    if (i < n4) {
        float4 v = src[i];
        __half2 h0 = __floats2half2_rn(v.x, v.y);
        __half2 h1 = __floats2half2_rn(v.z, v.w);
        uint2 o;
        o.x = *(uint32_t*)&h0;
        o.y = *(uint32_t*)&h1;
        dst[i] = o;
    }
}

// ---------------------------------------------------------------------------
// Batched weight transpose + fp16: dst[n][k] = fp16(src[k][n])
// ---------------------------------------------------------------------------
struct SrcArr16 { const float* p[16]; };
struct SrcArr2  { const float* p[2]; };

template <typename SA>
__global__ void __launch_bounds__(256)
transpose_kernel(SA srcs, __half* __restrict__ dstbase, int K, size_t dst_stride)
{
    __shared__ float t[32][33];
    const float* src = srcs.p[blockIdx.z];
    __half* dst = dstbase + (size_t)blockIdx.z * dst_stride;
    const int n0 = blockIdx.x * 32, k0 = blockIdx.y * 32;
    const int tx = threadIdx.x, ty = threadIdx.y;
#pragma unroll
    for (int j = 0; j < 32; j += 8)
        t[ty + j][tx] = src[(size_t)(k0 + ty + j) * GN + n0 + tx];
    __syncthreads();
#pragma unroll
    for (int j = 0; j < 32; j += 8)
        dst[(size_t)(n0 + ty + j) * K + k0 + tx] = __float2half(t[tx][ty + j]);
}

// ---------------------------------------------------------------------------
// Attention kernels
// ---------------------------------------------------------------------------
__global__ void __launch_bounds__(256)
qk_kernel(const float* __restrict__ Q, const float* __restrict__ K,
          float* __restrict__ S,
          const int* __restrict__ qm, const int* __restrict__ km,
          int Lq, int Lk, float scale)
{
    __shared__ float Qs[96][33];
    __shared__ float Ks[96][33];

    const int bh = blockIdx.x;
    const int b  = bh >> 2;
    const int h  = bh & 3;
    const int tid = threadIdx.x;
    const int tx  = tid & 15;
    const int ty  = tid >> 4;

    float acc[6][6];
#pragma unroll
    for (int i = 0; i < 6; i++)
#pragma unroll
        for (int j = 0; j < 6; j++) acc[i][j] = 0.0f;

    for (int dd = 0; dd < DHv; dd += 32) {
        for (int idx = tid; idx < 96 * 32; idx += 256) {
            const int q = idx >> 5, d = idx & 31;
            Qs[q][d] = (q < Lq) ? Q[(size_t)(b * Lq + q) * Dv + h * DHv + dd + d] : 0.0f;
        }
        for (int idx = tid; idx < 96 * 32; idx += 256) {
            const int k = idx >> 5, d = idx & 31;
            Ks[k][d] = (k < Lk) ? K[(size_t)(b * Lk + k) * Dv + h * DHv + dd + d] : 0.0f;
        }
        __syncthreads();

#pragma unroll
        for (int d = 0; d < 32; d++) {
            float qa[6], kb[6];
#pragma unroll
            for (int i = 0; i < 6; i++) qa[i] = Qs[ty + 16 * i][d];
#pragma unroll
            for (int j = 0; j < 6; j++) kb[j] = Ks[tx + 16 * j][d];
#pragma unroll
            for (int i = 0; i < 6; i++)
#pragma unroll
                for (int j = 0; j < 6; j++)
                    acc[i][j] += qa[i] * kb[j];
        }
        __syncthreads();
    }

#pragma unroll
    for (int i = 0; i < 6; i++) {
        const int q = ty + 16 * i;
        if (q >= Lq) continue;
        const int qok = qm[b * Lq + q];
#pragma unroll
        for (int j = 0; j < 6; j++) {
            const int k = tx + 16 * j;
            if (k >= Lk) continue;
            const bool ok = (qok != 0) && (km[b * Lk + k] != 0);
            S[((size_t)bh * Lq + q) * Lk + k] = ok ? acc[i][j] * scale : NEGF;
        }
    }
}

__global__ void __launch_bounds__(128)
softmax_kernel(float* __restrict__ S, int Lk)
{
    const int row = blockIdx.x * 4 + (threadIdx.x >> 5);
    const int l   = threadIdx.x & 31;
    float* s = S + (size_t)row * Lk;

    float v0 = (l      < Lk) ? s[l]      : -3.4e38f;
    float v1 = (l + 32 < Lk) ? s[l + 32] : -3.4e38f;
    float v2 = (l + 64 < Lk) ? s[l + 64] : -3.4e38f;

    float mx = fmaxf(v0, fmaxf(v1, v2));
#pragma unroll
    for (int o = 16; o; o >>= 1) mx = fmaxf(mx, __shfl_xor_sync(0xffffffffu, mx, o));

    float e0 = (l      < Lk && v0 != NEGF) ? __expf(v0 - mx) : 0.0f;
    float e1 = (l + 32 < Lk && v1 != NEGF) ? __expf(v1 - mx) : 0.0f;
    float e2 = (l + 64 < Lk && v2 != NEGF) ? __expf(v2 - mx) : 0.0f;

    float sum = e0 + e1 + e2;
#pragma unroll
    for (int o = 16; o; o >>= 1) sum += __shfl_xor_sync(0xffffffffu, sum, o);

    const float inv = (sum > 0.0f) ? (1.0f / sum) : 0.0f;
    if (l      < Lk) s[l]      = e0 * inv;
    if (l + 32 < Lk) s[l + 32] = e1 * inv;
    if (l + 64 < Lk) s[l + 64] = e2 * inv;
}

// AV: writes fp16 output directly (only consumed by the Wo GEMM)
__global__ void __launch_bounds__(256)
av_kernel(const float* __restrict__ S, const float* __restrict__ V,
          __half* __restrict__ AO16, int Lq, int Lk)
{
    __shared__ float Ss[96][33];
    __shared__ float Vs[32][65];

    const int bh = blockIdx.x;
    const int b  = bh >> 2;
    const int h  = bh & 3;
    const int dt = blockIdx.y;
    const int tid = threadIdx.x;
    const int tx  = tid & 15;
    const int ty  = tid >> 4;

    float acc[6][4];
#pragma unroll
    for (int i = 0; i < 6; i++)
#pragma unroll
        for (int j = 0; j < 4; j++) acc[i][j] = 0.0f;

    for (int kk = 0; kk < Lk; kk += 32) {
        for (int idx = tid; idx < 96 * 32; idx += 256) {
            const int q = idx >> 5, k = idx & 31;
            Ss[q][k] = (q < Lq) ? S[((size_t)bh * Lq + q) * Lk + kk + k] : 0.0f;
        }
        for (int idx = tid; idx < 32 * 64; idx += 256) {
            const int kr = idx >> 6, dc = idx & 63;
            Vs[kr][dc] = V[(size_t)(b * Lk + kk + kr) * Dv + h * DHv + dt * 64 + dc];
        }
        __syncthreads();

#pragma unroll
        for (int k = 0; k < 32; k++) {
            float sa[6], vb[4];
#pragma unroll
            for (int i = 0; i < 6; i++) sa[i] = Ss[ty + 16 * i][k];
#pragma unroll
            for (int j = 0; j < 4; j++) vb[j] = Vs[k][tx + 16 * j];
#pragma unroll
            for (int i = 0; i < 6; i++)
#pragma unroll
                for (int j = 0; j < 4; j++)
                    acc[i][j] += sa[i] * vb[j];
        }
        __syncthreads();
    }

#pragma unroll
    for (int i = 0; i < 6; i++) {
        const int q = ty + 16 * i;
        if (q >= Lq) continue;
#pragma unroll
        for (int j = 0; j < 4; j++) {
            AO16[(size_t)(b * Lq + q) * Dv + h * DHv + dt * 64 + tx + 16 * j] =
                __float2half(acc[i][j]);
        }
    }
}

// LayerNorm; optional fp16 copy of the output
__global__ void __launch_bounds__(256)
ln_kernel(const float* __restrict__ X, const float* __restrict__ g,
          const float* __restrict__ b, float* __restrict__ Y,
          __half* __restrict__ Y16)
{
    const int row = blockIdx.x;
    const int t   = threadIdx.x;
    const float4 v = ((const float4*)(X + (size_t)row * Dv))[t];

    float s  = v.x + v.y + v.z + v.w;
    float ss = v.x * v.x + v.y * v.y + v.z * v.z + v.w * v.w;

    __shared__ float shs[8], shq[8];
#pragma unroll
    for (int o = 16; o; o >>= 1) {
        s  += __shfl_xor_sync(0xffffffffu, s,  o);
        ss += __shfl_xor_sync(0xffffffffu, ss, o);
    }
    const int w = t >> 5, l = t & 31;
    if (l == 0) { shs[w] = s; shq[w] = ss; }
    __syncthreads();
    float m = 0.0f, q = 0.0f;
#pragma unroll
    for (int i = 0; i < 8; i++) { m += shs[i]; q += shq[i]; }
    m *= (1.0f / Dv);
    q  = q * (1.0f / Dv) - m * m;
    const float r = rsqrtf(q + 1e-3f);

    const float4 gv = ((const float4*)g)[t];
    const float4 bv = ((const float4*)b)[t];
    float4 o;
    o.x = (v.x - m) * r * gv.x + bv.x;
    o.y = (v.y - m) * r * gv.y + bv.y;
    o.z = (v.z - m) * r * gv.z + bv.z;
    o.w = (v.w - m) * r * gv.w + bv.w;
    ((float4*)(Y + (size_t)row * Dv))[t] = o;
    if (Y16) {
        __half2 h0 = __floats2half2_rn(o.x, o.y);
        __half2 h1 = __floats2half2_rn(o.z, o.w);
        uint2 u;
        u.x = *(uint32_t*)&h0;
        u.y = *(uint32_t*)&h1;
        ((uint2*)(Y16 + (size_t)row * Dv))[t] = u;
    }
}

// ---------------------------------------------------------------------------
// Host orchestration
// ---------------------------------------------------------------------------
static inline void gemm(const __half* A, const __half* Wt, const float* bias,
                        float* C, __half* C16, int M, int K)
{
    dim3 grid(GN / 128, M / 128);
    hgemm_kernel<<<grid, 256, SMEM_BYTES>>>(A, Wt, bias, C, C16, M, K);
}

static inline void attention(const float* Q, const float* K, const float* V,
                             float* S, __half* AO16,
                             const int* qm, const int* km, int Lq, int Lk)
{
    qk_kernel<<<BHv, 256>>>(Q, K, S, qm, km, Lq, Lk, 0.0625f);
    softmax_kernel<<<BHv * Lq / 4, 128>>>(S, Lk);
    av_kernel<<<dim3(BHv, 4), 256>>>(S, V, AO16, Lq, Lk);
}

extern "C" void kernel_launch(void* const* d_in, const int* in_sizes, int n_in,
                              void* d_out, int out_size)
{
    const float* text_emb  = (const float*)d_in[0];
    const float* image_emb = (const float*)d_in[1];
    const int*   text_mask  = (const int*)d_in[2];
    const int*   image_mask = (const int*)d_in[3];
    const float* W_tp = (const float*)d_in[4];
    const float* b_tp = (const float*)d_in[5];
    const float* W_ip = (const float*)d_in[6];
    const float* b_ip = (const float*)d_in[7];
    const float* ta_Wq = (const float*)d_in[8];
    const float* ta_Wk = (const float*)d_in[9];
    const float* ta_Wv = (const float*)d_in[10];
    const float* ta_Wo = (const float*)d_in[11];
    const float* ia_Wq = (const float*)d_in[12];
    const float* ia_Wk = (const float*)d_in[13];
    const float* ia_Wv = (const float*)d_in[14];
    const float* ia_Wo = (const float*)d_in[15];
    const float* ts_Wq = (const float*)d_in[16];
    const float* ts_Wk = (const float*)d_in[17];
    const float* ts_Wv = (const float*)d_in[18];
    const float* ts_Wo = (const float*)d_in[19];
    const float* is_Wq = (const float*)d_in[20];
    const float* is_Wk = (const float*)d_in[21];
    const float* is_Wv = (const float*)d_in[22];
    const float* is_Wo = (const float*)d_in[23];
    const float* ln_ta_g = (const float*)d_in[24];
    const float* ln_ta_b = (const float*)d_in[25];
    const float* ln_ia_g = (const float*)d_in[26];
    const float* ln_ia_b = (const float*)d_in[27];
    const float* ln_ts_g = (const float*)d_in[28];
    const float* ln_ts_b = (const float*)d_in[29];
    const float* ln_is_g = (const float*)d_in[30];
    const float* ln_is_b = (const float*)d_in[31];

    float* out_text = (float*)d_out;
    float* out_img  = (float*)d_out + (size_t)Bv * LIv * Dv;

    float *Pt, *Pi, *Q, *K, *V, *S, *Xt, *Xi;
    __half *tE16, *iE16, *Pt16, *Pi16, *AO16, *Xt16, *Xi16, *Wh;
    cudaGetSymbolAddress((void**)&Pt, g_Pt);
    cudaGetSymbolAddress((void**)&Pi, g_Pi);
    cudaGetSymbolAddress((void**)&Q,  g_Qb);
    cudaGetSymbolAddress((void**)&K,  g_Kb);
    cudaGetSymbolAddress((void**)&V,  g_Vb);
    cudaGetSymbolAddress((void**)&S,  g_Sb);
    cudaGetSymbolAddress((void**)&Xt, g_Xt);
    cudaGetSymbolAddress((void**)&Xi, g_Xi);
    cudaGetSymbolAddress((void**)&tE16, g_tE16);
    cudaGetSymbolAddress((void**)&iE16, g_iE16);
    cudaGetSymbolAddress((void**)&Pt16, g_Pt16);
    cudaGetSymbolAddress((void**)&Pi16, g_Pi16);
    cudaGetSymbolAddress((void**)&AO16, g_AO16);
    cudaGetSymbolAddress((void**)&Xt16, g_Xt16);
    cudaGetSymbolAddress((void**)&Xi16, g_Xi16);
    cudaGetSymbolAddress((void**)&Wh, g_Wh);

    cudaFuncSetAttribute(hgemm_kernel,
                         cudaFuncAttributeMaxDynamicSharedMemorySize, SMEM_BYTES);

    // ---- fp16 conversions of raw embeddings ----
    {
        const int n4t = Bv * LTv * DTv / 4;   // 3145728
        f2h_kernel<<<n4t / 256, 256>>>((const float4*)text_emb, (uint2*)tE16, n4t);
        const int n4i = Bv * LIv * DIv / 4;   // 4194304
        f2h_kernel<<<n4i / 256, 256>>>((const float4*)image_emb, (uint2*)iE16, n4i);
    }

    // ---- transpose + fp16 all weights ----
    SrcArr16 s16;
    s16.p[0]  = W_tp;  s16.p[1]  = ta_Wq; s16.p[2]  = ta_Wk; s16.p[3]  = ta_Wv;
    s16.p[4]  = ta_Wo; s16.p[5]  = ia_Wq; s16.p[6]  = ia_Wk; s16.p[7]  = ia_Wo;
    s16.p[8]  = ts_Wq; s16.p[9]  = ts_Wk; s16.p[10] = ts_Wv; s16.p[11] = ts_Wo;
    s16.p[12] = is_Wq; s16.p[13] = is_Wk; s16.p[14] = is_Wv; s16.p[15] = is_Wo;
    transpose_kernel<SrcArr16><<<dim3(32, 32, 16), dim3(32, 8)>>>(s16, Wh, 1024, 1 << 20);

    __half* Wh2 = Wh + ((size_t)16 << 20);
    SrcArr2 s2;
    s2.p[0] = W_ip; s2.p[1] = ia_Wv;
    transpose_kernel<SrcArr2><<<dim3(32, 64, 2), dim3(32, 8)>>>(s2, Wh2, 2048, 1 << 21);

    #define WH(i)  (Wh + ((size_t)(i) << 20))
    const __half* tW_tp  = WH(0);
    const __half* tta_Wq = WH(1);  const __half* tta_Wk = WH(2);
    const __half* tta_Wv = WH(3);  const __half* tta_Wo = WH(4);
    const __half* tia_Wq = WH(5);  const __half* tia_Wk = WH(6);
    const __half* tia_Wo = WH(7);
    const __half* tts_Wq = WH(8);  const __half* tts_Wk = WH(9);
    const __half* tts_Wv = WH(10); const __half* tts_Wo = WH(11);
    const __half* tis_Wq = WH(12); const __half* tis_Wk = WH(13);
    const __half* tis_Wv = WH(14); const __half* tis_Wo = WH(15);
    const __half* tW_ip  = Wh2;
    const __half* tia_Wv = Wh2 + ((size_t)1 << 21);

    const int Mt = Bv * LTv;   // 12288
    const int Mi = Bv * LIv;   // 8192

    // Projections (also emit fp16 copies used as downstream GEMM A-operands)
    gemm(tE16, tW_tp, b_tp, Pt, Pt16, Mt, 1024);
    gemm(iE16, tW_ip, b_ip, Pi, Pi16, Mi, 2048);

    // --- text cross-attn: q=image_proj, k=text_proj, v=raw text ---
    gemm(Pi16, tta_Wq, nullptr, Q, nullptr, Mi, 1024);
    gemm(Pt16, tta_Wk, nullptr, K, nullptr, Mt, 1024);
    gemm(tE16, tta_Wv, nullptr, V, nullptr, Mt, 1024);
    attention(Q, K, V, S, AO16, image_mask, text_mask, LIv, LTv);
    gemm(AO16, tta_Wo, nullptr, Q, nullptr, Mi, 1024);
    ln_kernel<<<Mi, 256>>>(Q, ln_ta_g, ln_ta_b, Xt, Xt16);

    // --- image cross-attn: q=text_proj, k=image_proj, v=raw image ---
    gemm(Pt16, tia_Wq, nullptr, Q, nullptr, Mt, 1024);
    gemm(Pi16, tia_Wk, nullptr, K, nullptr, Mi, 1024);
    gemm(iE16, tia_Wv, nullptr, V, nullptr, Mi, 2048);
    attention(Q, K, V, S, AO16, text_mask, image_mask, LTv, LIv);
    gemm(AO16, tia_Wo, nullptr, Q, nullptr, Mt, 1024);
    ln_kernel<<<Mt, 256>>>(Q, ln_ia_g, ln_ia_b, Xi, Xi16);

    // --- text self-attn (on Xt [B,LI,D], masks = image_mask) ---
    gemm(Xt16, tts_Wq, nullptr, Q, nullptr, Mi, 1024);
    gemm(Xt16, tts_Wk, nullptr, K, nullptr, Mi, 1024);
    gemm(Xt16, tts_Wv, nullptr, V, nullptr, Mi, 1024);
    attention(Q, K, V, S, AO16, image_mask, image_mask, LIv, LIv);
    gemm(AO16, tts_Wo, nullptr, Q, nullptr, Mi, 1024);
    ln_kernel<<<Mi, 256>>>(Q, ln_ts_g, ln_ts_b, out_text, nullptr);

    // --- image self-attn (on Xi [B,LT,D], masks = text_mask) ---
    gemm(Xi16, tis_Wq, nullptr, Q, nullptr, Mt, 1024);
    gemm(Xi16, tis_Wk, nullptr, K, nullptr, Mt, 1024);
    gemm(Xi16, tis_Wv, nullptr, V, nullptr, Mt, 1024);
    attention(Q, K, V, S, AO16, text_mask, text_mask, LTv, LTv);
    gemm(AO16, tis_Wo, nullptr, Q, nullptr, Mt, 1024);
    ln_kernel<<<Mt, 256>>>(Q, ln_is_g, ln_is_b, out_img, nullptr);
}

// round 5
// speedup vs baseline: 6.0205x; 1.2044x over previous
#include <cuda_runtime.h>
#include <cuda_fp16.h>
#include <cstdint>

// ---------------------------------------------------------------------------
// Problem dims
// ---------------------------------------------------------------------------
#define Bv   128
#define LTv  96
#define LIv  64
#define Dv   1024
#define Hv   4
#define DHv  256
#define DTv  1024
#define DIv  2048
#define BHv  (Bv * Hv)    // 512

#define NEGF (-2147483648.0f)   // -2^31

// ---------------------------------------------------------------------------
// Scratch buffers
// ---------------------------------------------------------------------------
static __device__ __half g_tE16[(size_t)Bv * LTv * DTv];
static __device__ __half g_iE16[(size_t)Bv * LIv * DIv];
static __device__ __half g_Pt16[(size_t)Bv * LTv * Dv];
static __device__ __half g_Pi16[(size_t)Bv * LIv * Dv];
// branch T (text_att -> out_text)
static __device__ __half g_QT[(size_t)Bv * LIv * Dv];
static __device__ __half g_KT[(size_t)Bv * LTv * Dv];
static __device__ __half g_VT[(size_t)Bv * LTv * Dv];
static __device__ __half g_AOT[(size_t)Bv * LIv * Dv];
static __device__ __half g_XT[(size_t)Bv * LIv * Dv];
static __device__ __half g_QKVT[(size_t)Bv * LIv * Dv * 3];
static __device__ float  g_CT[(size_t)Bv * LIv * Dv];
// branch I (image_att -> out_img)
static __device__ __half g_QI[(size_t)Bv * LTv * Dv];
static __device__ __half g_KI[(size_t)Bv * LIv * Dv];
static __device__ __half g_VI[(size_t)Bv * LIv * Dv];
static __device__ __half g_AOI[(size_t)Bv * LTv * Dv];
static __device__ __half g_XI[(size_t)Bv * LTv * Dv];
static __device__ __half g_QKVI[(size_t)Bv * LTv * Dv * 3];
static __device__ float  g_CI[(size_t)Bv * LTv * Dv];
// transposed fp16 weights: 16 x [1024,1024] + 2 x [1024,2048]
static __device__ __half g_Wh[(size_t)16 * 1024 * 1024 + (size_t)2 * 1024 * 2048];

// ---------------------------------------------------------------------------
// PTX helpers
// ---------------------------------------------------------------------------
__device__ __forceinline__ uint32_t smem_u32(const void* p) {
    uint32_t a;
    asm("{ .reg .u64 t; cvta.to.shared.u64 t, %1; cvt.u32.u64 %0, t; }" : "=r"(a) : "l"(p));
    return a;
}
#define CP_COMMIT() asm volatile("cp.async.commit_group;" ::: "memory")
#define CP_WAIT1()  asm volatile("cp.async.wait_group 1;" ::: "memory")
#define CP_WAIT0()  asm volatile("cp.async.wait_group 0;" ::: "memory")

__device__ __forceinline__ void cp16(uint32_t dst, const void* src) {
    asm volatile("cp.async.cg.shared.global [%0], [%1], 16;" :: "r"(dst), "l"(src));
}
__device__ __forceinline__ void ldsm4(uint32_t& r0, uint32_t& r1, uint32_t& r2,
                                      uint32_t& r3, uint32_t addr) {
    asm volatile("ldmatrix.sync.aligned.m8n8.x4.shared.b16 {%0,%1,%2,%3}, [%4];"
                 : "=r"(r0), "=r"(r1), "=r"(r2), "=r"(r3) : "r"(addr));
}
__device__ __forceinline__ void mma_f16(float* c, uint32_t a0, uint32_t a1,
                                        uint32_t a2, uint32_t a3,
                                        uint32_t b0, uint32_t b1) {
    asm volatile(
        "mma.sync.aligned.m16n8k16.row.col.f32.f16.f16.f32 "
        "{%0,%1,%2,%3}, {%4,%5,%6,%7}, {%8,%9}, {%0,%1,%2,%3};"
        : "+f"(c[0]), "+f"(c[1]), "+f"(c[2]), "+f"(c[3])
        : "r"(a0), "r"(a1), "r"(a2), "r"(a3), "r"(b0), "r"(b1));
}

// ---------------------------------------------------------------------------
// fp16 mma GEMM: C[M,N] = A16[M,K] @ W[K,N] (+bias).  C fp32 and/or C16 fp16.
// A16 row-major [M,K]; Wt row-major [N,K] (transposed weight, fp16).
// CTA 128x128, 8 warps (2m x 4n), warp tile 64x32, BK=64, 2-stage cp.async.
// ---------------------------------------------------------------------------
#define STAGE_BYTES 32768u
#define SMEM_BYTES  (2 * STAGE_BYTES)

__device__ __forceinline__ void load_chunk_h(uint32_t sb, int s,
                                             const __half* __restrict__ A,
                                             const __half* __restrict__ Wt,
                                             int K, int kk, int bm, int bn, int tid)
{
    const uint32_t uA = sb + s * STAGE_BYTES;
    const uint32_t uB = uA + 16384u;
#pragma unroll
    for (int j = 0; j < 4; j++) {
        int idx = tid + 256 * j;
        int row = idx >> 3, seg = idx & 7;
        cp16(uA + row * 128 + ((seg ^ (row & 7)) << 4),
             A + (size_t)(bm + row) * K + kk + seg * 8);
    }
#pragma unroll
    for (int j = 0; j < 4; j++) {
        int idx = tid + 256 * j;
        int row = idx >> 3, seg = idx & 7;
        cp16(uB + row * 128 + ((seg ^ (row & 7)) << 4),
             Wt + (size_t)(bn + row) * K + kk + seg * 8);
    }
    CP_COMMIT();
}

__global__ void __launch_bounds__(256, 2)
hgemm_kernel(const __half* __restrict__ A, const __half* __restrict__ Wt,
             const float* __restrict__ bias, float* __restrict__ C,
             __half* __restrict__ C16, int M, int N, int K)
{
    extern __shared__ char smc[];
    const uint32_t sb = smem_u32(smc);
    const int tid  = threadIdx.x;
    const int lane = tid & 31;
    const int warp = tid >> 5;
    const int wm   = warp >> 2;
    const int wn   = warp & 3;
    const int bm   = blockIdx.y * 128;
    const int bn   = blockIdx.x * 128;

    const int lane15 = lane & 15;
    const int hi     = lane >> 4;

    int arow[4], brow[2];
#pragma unroll
    for (int mi = 0; mi < 4; mi++) arow[mi] = wm * 64 + mi * 16 + lane15;
#pragma unroll
    for (int nb = 0; nb < 2; nb++) brow[nb] = wn * 32 + nb * 16 + lane15;

    float acc[4][4][4];
#pragma unroll
    for (int mi = 0; mi < 4; mi++)
#pragma unroll
        for (int ni = 0; ni < 4; ni++)
#pragma unroll
            for (int r = 0; r < 4; r++) acc[mi][ni][r] = 0.0f;

    const int NC = K >> 6;
    load_chunk_h(sb, 0, A, Wt, K, 0,  bm, bn, tid);
    load_chunk_h(sb, 1, A, Wt, K, 64, bm, bn, tid);

    for (int i = 0; i < NC; i++) {
        const int s = i & 1;
        if (i < NC - 1) CP_WAIT1(); else CP_WAIT0();
        __syncthreads();

        const uint32_t uA = sb + s * STAGE_BYTES;
        const uint32_t uB = uA + 16384u;

#pragma unroll
        for (int ks = 0; ks < 4; ks++) {
            const int sg = ks * 2 + hi;
            uint32_t bf[4][2];
#pragma unroll
            for (int nb = 0; nb < 2; nb++) {
                uint32_t r0, r1, r2, r3;
                ldsm4(r0, r1, r2, r3,
                      uB + brow[nb] * 128 + ((sg ^ (brow[nb] & 7)) << 4));
                bf[nb * 2][0]     = r0; bf[nb * 2][1]     = r2;
                bf[nb * 2 + 1][0] = r1; bf[nb * 2 + 1][1] = r3;
            }
#pragma unroll
            for (int mi = 0; mi < 4; mi++) {
                uint32_t a0, a1, a2, a3;
                ldsm4(a0, a1, a2, a3,
                      uA + arow[mi] * 128 + ((sg ^ (arow[mi] & 7)) << 4));
#pragma unroll
                for (int ni = 0; ni < 4; ni++)
                    mma_f16(acc[mi][ni], a0, a1, a2, a3, bf[ni][0], bf[ni][1]);
            }
        }
        __syncthreads();
        if (i + 2 < NC) load_chunk_h(sb, s, A, Wt, K, (i + 2) * 64, bm, bn, tid);
    }

    const int qr = lane >> 2, qc = lane & 3;
#pragma unroll
    for (int mi = 0; mi < 4; mi++) {
        const int row = bm + wm * 64 + mi * 16 + qr;
#pragma unroll
        for (int ni = 0; ni < 4; ni++) {
            const int col = bn + wn * 32 + ni * 8 + qc * 2;
            float2 v0 = make_float2(acc[mi][ni][0], acc[mi][ni][1]);
            float2 v1 = make_float2(acc[mi][ni][2], acc[mi][ni][3]);
            if (bias) {
                const float2 bz = *(const float2*)(bias + col);
                v0.x += bz.x; v0.y += bz.y;
                v1.x += bz.x; v1.y += bz.y;
            }
            if (C) {
                *(float2*)(C + (size_t)row * N + col)       = v0;
                *(float2*)(C + (size_t)(row + 8) * N + col) = v1;
            }
            if (C16) {
                __half2 h0 = __floats2half2_rn(v0.x, v0.y);
                __half2 h1 = __floats2half2_rn(v1.x, v1.y);
                *(__half2*)(C16 + (size_t)row * N + col)       = h0;
                *(__half2*)(C16 + (size_t)(row + 8) * N + col) = h1;
            }
        }
    }
}

// ---------------------------------------------------------------------------
// fp32 -> fp16 convert
// ---------------------------------------------------------------------------
__global__ void __launch_bounds__(256)
f2h_kernel(const float4* __restrict__ src, uint2* __restrict__ dst, int n4)
{
    const int i = blockIdx.x * 256 + threadIdx.x;
    if (i < n4) {
        float4 v = src[i];
        __half2 h0 = __floats2half2_rn(v.x, v.y);
        __half2 h1 = __floats2half2_rn(v.z, v.w);
        uint2 o;
        o.x = *(uint32_t*)&h0;
        o.y = *(uint32_t*)&h1;
        dst[i] = o;
    }
}

// ---------------------------------------------------------------------------
// Batched weight transpose + fp16: dst[n][k] = fp16(src[k][n])
// ---------------------------------------------------------------------------
struct SrcArr16 { const float* p[16]; };
struct SrcArr2  { const float* p[2]; };

template <typename SA>
__global__ void __launch_bounds__(256)
transpose_kernel(SA srcs, __half* __restrict__ dstbase, int K, size_t dst_stride)
{
    __shared__ float t[32][33];
    const float* src = srcs.p[blockIdx.z];
    __half* dst = dstbase + (size_t)blockIdx.z * dst_stride;
    const int n0 = blockIdx.x * 32, k0 = blockIdx.y * 32;
    const int tx = threadIdx.x, ty = threadIdx.y;
#pragma unroll
    for (int j = 0; j < 32; j += 8)
        t[ty + j][tx] = src[(size_t)(k0 + ty + j) * 1024 + n0 + tx];
    __syncthreads();
#pragma unroll
    for (int j = 0; j < 32; j += 8)
        dst[(size_t)(n0 + ty + j) * K + k0 + tx] = __float2half(t[tx][ty + j]);
}

// ---------------------------------------------------------------------------
// Fused attention: QK^T + mask -> softmax -> AV, one block per (b,h).
// Q/K/V fp16 with row strides sq/sk/sv; AO fp16 row stride 1024.
// Dynamic smem: Ss[96][97] + Qs[96][33] + Ks[96][33] (Vs aliases Qs).
// ---------------------------------------------------------------------------
#define ATTN_SMEM (15648 * 4)

__global__ void __launch_bounds__(256)
attn_kernel(const __half* __restrict__ Q, int sq,
            const __half* __restrict__ K, int sk,
            const __half* __restrict__ V, int sv,
            __half* __restrict__ AO,
            const int* __restrict__ qm, const int* __restrict__ km,
            int Lq, int Lk)
{
    extern __shared__ float sm[];
    float* Ss = sm;              // [96][97]
    float* Qs = sm + 9312;       // [96][33]
    float* Ks = sm + 12480;      // [96][33]
    float* Vs = Qs;              // [32][65] alias (phase 3)

    const int bh = blockIdx.x;
    const int b  = bh >> 2;
    const int h  = bh & 3;
    const int tid = threadIdx.x;
    const int tx  = tid & 15;
    const int ty  = tid >> 4;

    // ---- phase 1: scores ----
    float acc[6][6];
#pragma unroll
    for (int i = 0; i < 6; i++)
#pragma unroll
        for (int j = 0; j < 6; j++) acc[i][j] = 0.0f;

    for (int dd = 0; dd < DHv; dd += 32) {
        for (int idx = tid; idx < 96 * 32; idx += 256) {
            const int q = idx >> 5, d = idx & 31;
            Qs[q * 33 + d] = (q < Lq)
                ? __half2float(Q[(size_t)(b * Lq + q) * sq + h * DHv + dd + d]) : 0.0f;
        }
        for (int idx = tid; idx < 96 * 32; idx += 256) {
            const int k = idx >> 5, d = idx & 31;
            Ks[k * 33 + d] = (k < Lk)
                ? __half2float(K[(size_t)(b * Lk + k) * sk + h * DHv + dd + d]) : 0.0f;
        }
        __syncthreads();
#pragma unroll
        for (int d = 0; d < 32; d++) {
            float qa[6], kb[6];
#pragma unroll
            for (int i = 0; i < 6; i++) qa[i] = Qs[(ty + 16 * i) * 33 + d];
#pragma unroll
            for (int j = 0; j < 6; j++) kb[j] = Ks[(tx + 16 * j) * 33 + d];
#pragma unroll
            for (int i = 0; i < 6; i++)
#pragma unroll
                for (int j = 0; j < 6; j++)
                    acc[i][j] += qa[i] * kb[j];
        }
        __syncthreads();
    }

#pragma unroll
    for (int i = 0; i < 6; i++) {
        const int q = ty + 16 * i;
        if (q >= Lq) continue;
        const int qok = qm[b * Lq + q];
#pragma unroll
        for (int j = 0; j < 6; j++) {
            const int k = tx + 16 * j;
            if (k >= Lk) continue;
            const bool ok = (qok != 0) && (km[b * Lk + k] != 0);
            Ss[q * 97 + k] = ok ? acc[i][j] * 0.0625f : NEGF;
        }
    }
    __syncthreads();

    // ---- phase 2: softmax (one warp per row, rows strided by 8) ----
    const int w = tid >> 5, l = tid & 31;
    for (int r = w; r < Lq; r += 8) {
        float* s = Ss + r * 97;
        float v0 = (l      < Lk) ? s[l]      : -3.4e38f;
        float v1 = (l + 32 < Lk) ? s[l + 32] : -3.4e38f;
        float v2 = (l + 64 < Lk) ? s[l + 64] : -3.4e38f;

        float mx = fmaxf(v0, fmaxf(v1, v2));
#pragma unroll
        for (int o = 16; o; o >>= 1) mx = fmaxf(mx, __shfl_xor_sync(0xffffffffu, mx, o));

        float e0 = (l      < Lk && v0 != NEGF) ? __expf(v0 - mx) : 0.0f;
        float e1 = (l + 32 < Lk && v1 != NEGF) ? __expf(v1 - mx) : 0.0f;
        float e2 = (l + 64 < Lk && v2 != NEGF) ? __expf(v2 - mx) : 0.0f;

        float sum = e0 + e1 + e2;
#pragma unroll
        for (int o = 16; o; o >>= 1) sum += __shfl_xor_sync(0xffffffffu, sum, o);

        const float inv = (sum > 0.0f) ? (1.0f / sum) : 0.0f;
        if (l      < Lk) s[l]      = e0 * inv;
        if (l + 32 < Lk) s[l + 32] = e1 * inv;
        if (l + 64 < Lk) s[l + 64] = e2 * inv;
    }
    __syncthreads();

    // ---- phase 3: AV ----
    for (int dt = 0; dt < 4; dt++) {
        float a2[6][4];
#pragma unroll
        for (int i = 0; i < 6; i++)
#pragma unroll
            for (int j = 0; j < 4; j++) a2[i][j] = 0.0f;

        for (int kk = 0; kk < Lk; kk += 32) {
            for (int idx = tid; idx < 32 * 64; idx += 256) {
                const int kr = idx >> 6, dc = idx & 63;
                Vs[kr * 65 + dc] =
                    __half2float(V[(size_t)(b * Lk + kk + kr) * sv + h * DHv + dt * 64 + dc]);
            }
            __syncthreads();
#pragma unroll
            for (int k = 0; k < 32; k++) {
                float sa[6], vb[4];
#pragma unroll
                for (int i = 0; i < 6; i++) sa[i] = Ss[(ty + 16 * i) * 97 + kk + k];
#pragma unroll
                for (int j = 0; j < 4; j++) vb[j] = Vs[k * 65 + tx + 16 * j];
#pragma unroll
                for (int i = 0; i < 6; i++)
#pragma unroll
                    for (int j = 0; j < 4; j++)
                        a2[i][j] += sa[i] * vb[j];
            }
            __syncthreads();
        }
#pragma unroll
        for (int i = 0; i < 6; i++) {
            const int q = ty + 16 * i;
            if (q >= Lq) continue;
#pragma unroll
            for (int j = 0; j < 4; j++) {
                AO[(size_t)(b * Lq + q) * Dv + h * DHv + dt * 64 + tx + 16 * j] =
                    __float2half(a2[i][j]);
            }
        }
    }
}

// ---------------------------------------------------------------------------
// LayerNorm; fp32 out and/or fp16 out (either may be null)
// ---------------------------------------------------------------------------
__global__ void __launch_bounds__(256)
ln_kernel(const float* __restrict__ X, const float* __restrict__ g,
          const float* __restrict__ b, float* __restrict__ Y,
          __half* __restrict__ Y16)
{
    const int row = blockIdx.x;
    const int t   = threadIdx.x;
    const float4 v = ((const float4*)(X + (size_t)row * Dv))[t];

    float s  = v.x + v.y + v.z + v.w;
    float ss = v.x * v.x + v.y * v.y + v.z * v.z + v.w * v.w;

    __shared__ float shs[8], shq[8];
#pragma unroll
    for (int o = 16; o; o >>= 1) {
        s  += __shfl_xor_sync(0xffffffffu, s,  o);
        ss += __shfl_xor_sync(0xffffffffu, ss, o);
    }
    const int w = t >> 5, l = t & 31;
    if (l == 0) { shs[w] = s; shq[w] = ss; }
    __syncthreads();
    float m = 0.0f, q = 0.0f;
#pragma unroll
    for (int i = 0; i < 8; i++) { m += shs[i]; q += shq[i]; }
    m *= (1.0f / Dv);
    q  = q * (1.0f / Dv) - m * m;
    const float r = rsqrtf(q + 1e-3f);

    const float4 gv = ((const float4*)g)[t];
    const float4 bv = ((const float4*)b)[t];
    float4 o;
    o.x = (v.x - m) * r * gv.x + bv.x;
    o.y = (v.y - m) * r * gv.y + bv.y;
    o.z = (v.z - m) * r * gv.z + bv.z;
    o.w = (v.w - m) * r * gv.w + bv.w;
    if (Y) ((float4*)(Y + (size_t)row * Dv))[t] = o;
    if (Y16) {
        __half2 h0 = __floats2half2_rn(o.x, o.y);
        __half2 h1 = __floats2half2_rn(o.z, o.w);
        uint2 u;
        u.x = *(uint32_t*)&h0;
        u.y = *(uint32_t*)&h1;
        ((uint2*)(Y16 + (size_t)row * Dv))[t] = u;
    }
}

// ---------------------------------------------------------------------------
// Host orchestration
// ---------------------------------------------------------------------------
static inline void gemm(cudaStream_t st, const __half* A, const __half* Wt,
                        const float* bias, float* C, __half* C16,
                        int M, int N, int K)
{
    dim3 grid(N / 128, M / 128);
    hgemm_kernel<<<grid, 256, SMEM_BYTES, st>>>(A, Wt, bias, C, C16, M, N, K);
}

extern "C" void kernel_launch(void* const* d_in, const int* in_sizes, int n_in,
                              void* d_out, int out_size)
{
    const float* text_emb  = (const float*)d_in[0];
    const float* image_emb = (const float*)d_in[1];
    const int*   text_mask  = (const int*)d_in[2];
    const int*   image_mask = (const int*)d_in[3];
    const float* W_tp = (const float*)d_in[4];
    const float* b_tp = (const float*)d_in[5];
    const float* W_ip = (const float*)d_in[6];
    const float* b_ip = (const float*)d_in[7];
    const float* ta_Wq = (const float*)d_in[8];
    const float* ta_Wk = (const float*)d_in[9];
    const float* ta_Wv = (const float*)d_in[10];
    const float* ta_Wo = (const float*)d_in[11];
    const float* ia_Wq = (const float*)d_in[12];
    const float* ia_Wk = (const float*)d_in[13];
    const float* ia_Wv = (const float*)d_in[14];
    const float* ia_Wo = (const float*)d_in[15];
    const float* ts_Wq = (const float*)d_in[16];
    const float* ts_Wk = (const float*)d_in[17];
    const float* ts_Wv = (const float*)d_in[18];
    const float* ts_Wo = (const float*)d_in[19];
    const float* is_Wq = (const float*)d_in[20];
    const float* is_Wk = (const float*)d_in[21];
    const float* is_Wv = (const float*)d_in[22];
    const float* is_Wo = (const float*)d_in[23];
    const float* ln_ta_g = (const float*)d_in[24];
    const float* ln_ta_b = (const float*)d_in[25];
    const float* ln_ia_g = (const float*)d_in[26];
    const float* ln_ia_b = (const float*)d_in[27];
    const float* ln_ts_g = (const float*)d_in[28];
    const float* ln_ts_b = (const float*)d_in[29];
    const float* ln_is_g = (const float*)d_in[30];
    const float* ln_is_b = (const float*)d_in[31];

    float* out_text = (float*)d_out;
    float* out_img  = (float*)d_out + (size_t)Bv * LIv * Dv;

    __half *tE16, *iE16, *Pt16, *Pi16, *Wh;
    __half *QT, *KT, *VT, *AOT, *XT, *QKVT;
    __half *QI, *KI, *VI, *AOI, *XI, *QKVI;
    float *CT, *CI;
    cudaGetSymbolAddress((void**)&tE16, g_tE16);
    cudaGetSymbolAddress((void**)&iE16, g_iE16);
    cudaGetSymbolAddress((void**)&Pt16, g_Pt16);
    cudaGetSymbolAddress((void**)&Pi16, g_Pi16);
    cudaGetSymbolAddress((void**)&Wh,   g_Wh);
    cudaGetSymbolAddress((void**)&QT,   g_QT);
    cudaGetSymbolAddress((void**)&KT,   g_KT);
    cudaGetSymbolAddress((void**)&VT,   g_VT);
    cudaGetSymbolAddress((void**)&AOT,  g_AOT);
    cudaGetSymbolAddress((void**)&XT,   g_XT);
    cudaGetSymbolAddress((void**)&QKVT, g_QKVT);
    cudaGetSymbolAddress((void**)&CT,   g_CT);
    cudaGetSymbolAddress((void**)&QI,   g_QI);
    cudaGetSymbolAddress((void**)&KI,   g_KI);
    cudaGetSymbolAddress((void**)&VI,   g_VI);
    cudaGetSymbolAddress((void**)&AOI,  g_AOI);
    cudaGetSymbolAddress((void**)&XI,   g_XI);
    cudaGetSymbolAddress((void**)&QKVI, g_QKVI);
    cudaGetSymbolAddress((void**)&CI,   g_CI);

    cudaFuncSetAttribute(hgemm_kernel,
                         cudaFuncAttributeMaxDynamicSharedMemorySize, SMEM_BYTES);
    cudaFuncSetAttribute(attn_kernel,
                         cudaFuncAttributeMaxDynamicSharedMemorySize, ATTN_SMEM);

    static cudaStream_t s1 = nullptr;
    static cudaEvent_t evFork = nullptr, evJoin = nullptr;
    if (!s1) {
        cudaStreamCreateWithFlags(&s1, cudaStreamNonBlocking);
        cudaEventCreateWithFlags(&evFork, cudaEventDisableTiming);
        cudaEventCreateWithFlags(&evJoin, cudaEventDisableTiming);
    }
    cudaStream_t s0 = (cudaStream_t)0;

    // ---- shared prologue (stream 0) ----
    {
        const int n4t = Bv * LTv * DTv / 4;
        f2h_kernel<<<n4t / 256, 256, 0, s0>>>((const float4*)text_emb, (uint2*)tE16, n4t);
        const int n4i = Bv * LIv * DIv / 4;
        f2h_kernel<<<n4i / 256, 256, 0, s0>>>((const float4*)image_emb, (uint2*)iE16, n4i);
    }

    SrcArr16 s16;
    s16.p[0]  = W_tp;  s16.p[1]  = ta_Wq; s16.p[2]  = ta_Wk; s16.p[3]  = ta_Wv;
    s16.p[4]  = ta_Wo; s16.p[5]  = ia_Wq; s16.p[6]  = ia_Wk; s16.p[7]  = ia_Wo;
    s16.p[8]  = ts_Wq; s16.p[9]  = ts_Wk; s16.p[10] = ts_Wv; s16.p[11] = ts_Wo;
    s16.p[12] = is_Wq; s16.p[13] = is_Wk; s16.p[14] = is_Wv; s16.p[15] = is_Wo;
    transpose_kernel<SrcArr16><<<dim3(32, 32, 16), dim3(32, 8), 0, s0>>>(s16, Wh, 1024, 1 << 20);

    __half* Wh2 = Wh + ((size_t)16 << 20);
    SrcArr2 s2;
    s2.p[0] = W_ip; s2.p[1] = ia_Wv;
    transpose_kernel<SrcArr2><<<dim3(32, 64, 2), dim3(32, 8), 0, s0>>>(s2, Wh2, 2048, 1 << 21);

    #define WH(i)  (Wh + ((size_t)(i) << 20))
    const __half* tW_tp   = WH(0);
    const __half* tta_Wq  = WH(1);  const __half* tta_Wk = WH(2);
    const __half* tta_Wv  = WH(3);  const __half* tta_Wo = WH(4);
    const __half* tia_Wq  = WH(5);  const __half* tia_Wk = WH(6);
    const __half* tia_Wo  = WH(7);
    const __half* tts_QKV = WH(8);   // ts_Wq, ts_Wk, ts_Wv contiguous -> [3072,1024]
    const __half* tts_Wo  = WH(11);
    const __half* tis_QKV = WH(12);  // is_Wq, is_Wk, is_Wv contiguous
    const __half* tis_Wo  = WH(15);
    const __half* tW_ip   = Wh2;
    const __half* tia_Wv  = Wh2 + ((size_t)1 << 21);

    const int Mt = Bv * LTv;   // 12288
    const int Mi = Bv * LIv;   // 8192

    // Projections (fp16 outputs only)
    gemm(s0, tE16, tW_tp, b_tp, nullptr, Pt16, Mt, 1024, 1024);
    gemm(s0, iE16, tW_ip, b_ip, nullptr, Pi16, Mi, 1024, 2048);

    // ---- fork: branch T on s1, branch I on s0 ----
    cudaEventRecord(evFork, s0);
    cudaStreamWaitEvent(s1, evFork, 0);

    // === branch T (text_att -> out_text) on s1 ===
    gemm(s1, Pi16, tta_Wq, nullptr, nullptr, QT, Mi, 1024, 1024);
    gemm(s1, Pt16, tta_Wk, nullptr, nullptr, KT, Mt, 1024, 1024);
    gemm(s1, tE16, tta_Wv, nullptr, nullptr, VT, Mt, 1024, 1024);
    attn_kernel<<<BHv, 256, ATTN_SMEM, s1>>>(QT, 1024, KT, 1024, VT, 1024,
                                             AOT, image_mask, text_mask, LIv, LTv);
    gemm(s1, AOT, tta_Wo, nullptr, CT, nullptr, Mi, 1024, 1024);
    ln_kernel<<<Mi, 256, 0, s1>>>(CT, ln_ta_g, ln_ta_b, nullptr, XT);
    gemm(s1, XT, tts_QKV, nullptr, nullptr, QKVT, Mi, 3072, 1024);
    attn_kernel<<<BHv, 256, ATTN_SMEM, s1>>>(QKVT, 3072, QKVT + 1024, 3072,
                                             QKVT + 2048, 3072,
                                             AOT, image_mask, image_mask, LIv, LIv);
    gemm(s1, AOT, tts_Wo, nullptr, CT, nullptr, Mi, 1024, 1024);
    ln_kernel<<<Mi, 256, 0, s1>>>(CT, ln_ts_g, ln_ts_b, out_text, nullptr);
    cudaEventRecord(evJoin, s1);

    // === branch I (image_att -> out_img) on s0 ===
    gemm(s0, Pt16, tia_Wq, nullptr, nullptr, QI, Mt, 1024, 1024);
    gemm(s0, Pi16, tia_Wk, nullptr, nullptr, KI, Mi, 1024, 1024);
    gemm(s0, iE16, tia_Wv, nullptr, nullptr, VI, Mi, 1024, 2048);
    attn_kernel<<<BHv, 256, ATTN_SMEM, s0>>>(QI, 1024, KI, 1024, VI, 1024,
                                             AOI, text_mask, image_mask, LTv, LIv);
    gemm(s0, AOI, tia_Wo, nullptr, CI, nullptr, Mt, 1024, 1024);
    ln_kernel<<<Mt, 256, 0, s0>>>(CI, ln_ia_g, ln_ia_b, nullptr, XI);
    gemm(s0, XI, tis_QKV, nullptr, nullptr, QKVI, Mt, 3072, 1024);
    attn_kernel<<<BHv, 256, ATTN_SMEM, s0>>>(QKVI, 3072, QKVI + 1024, 3072,
                                             QKVI + 2048, 3072,
                                             AOI, text_mask, text_mask, LTv, LTv);
    gemm(s0, AOI, tis_Wo, nullptr, CI, nullptr, Mt, 1024, 1024);
    ln_kernel<<<Mt, 256, 0, s0>>>(CI, ln_is_g, ln_is_b, out_img, nullptr);

    // ---- join ----
    cudaStreamWaitEvent(s0, evJoin, 0);
}